// round 12
// baseline (speedup 1.0000x reference)
#include <cuda_runtime.h>
#include <cuda_fp16.h>
#include <math.h>
#include <stdint.h>

#define BB 2
#define SS 2048
#define DD 2048
#define HH 16
#define KVH 4
#define HD 128
#define MM (BB*SS)        // 4096 rows
#define KVD (KVH*HD)      // 512
#define NQKV (DD + 2*KVD) // 3072 stacked rows

// ---------------- scratch (device globals; no allocation allowed) ----------
__device__ uint32_t g_xh   [(size_t)MM*DD/2];     // x as half2 words
__device__ uint32_t g_wqkvh[(size_t)NQKV*DD/2];   // wq|wk|wv stacked, half2
__device__ uint32_t g_woh  [(size_t)DD*DD/2];
__device__ uint32_t g_QtW[(size_t)MM*DD/2];       // roped+scaled Q [b,h,s,d] half2
__device__ uint32_t g_KtW[(size_t)MM*KVD/2];      // roped K        [b,kh,s,d]
__device__ uint32_t g_VtW[(size_t)MM*KVD/2];      // V              [b,kh,s,d]
__device__ uint32_t g_AttOh[(size_t)MM*DD/2];     // attention out  [b,s,h*d] half2

// ---------------- helpers ----------------------------------------------------
__device__ __forceinline__ uint32_t f2h2(float x, float y){
    __half2 h = __floats2half2_rn(x, y);       // .x = low = first elem
    return *(uint32_t*)&h;
}
__device__ __forceinline__ void mma16(float* c, const uint32_t* a, const uint32_t* b){
    asm volatile("mma.sync.aligned.m16n8k16.row.col.f32.f16.f16.f32 "
        "{%0,%1,%2,%3}, {%4,%5,%6,%7}, {%8,%9}, {%0,%1,%2,%3};"
        : "+f"(c[0]),"+f"(c[1]),"+f"(c[2]),"+f"(c[3])
        : "r"(a[0]),"r"(a[1]),"r"(a[2]),"r"(a[3]),"r"(b[0]),"r"(b[1]));
}
__device__ __forceinline__ void ldmx4(uint32_t* r, uint32_t addr){
    asm volatile("ldmatrix.sync.aligned.m8n8.x4.shared.b16 {%0,%1,%2,%3}, [%4];"
        : "=r"(r[0]),"=r"(r[1]),"=r"(r[2]),"=r"(r[3]) : "r"(addr));
}
#define CP_ASYNC16(dst, src) \
    asm volatile("cp.async.cg.shared.global [%0], [%1], 16;" :: "r"(dst), "l"(src))
#define CP_COMMIT() asm volatile("cp.async.commit_group;")
#define CP_WAIT1()  asm volatile("cp.async.wait_group 1;" ::: "memory")
#define CP_WAIT0()  asm volatile("cp.async.wait_group 0;" ::: "memory")

// ---------------- fp32 -> fp16 conversion prep -------------------------------
// float4-granular. wq/wk/wv stack into g_wqkvh (rows 0-2047 | 2048-2559 | 2560-3071)
__global__ void cvt_kernel(const float* __restrict__ x,  const float* __restrict__ wq,
                           const float* __restrict__ wk, const float* __restrict__ wv,
                           const float* __restrict__ wo){
    size_t i = (size_t)blockIdx.x*256 + threadIdx.x;   // float4 index
    const float* src; uint32_t* dst;
    if      (i < 2097152u){ src = x;  dst = g_xh;                              }
    else if (i < 3145728u){ src = wq; dst = g_wqkvh;            i -= 2097152u; }
    else if (i < 3407872u){ src = wk; dst = g_wqkvh + 2097152u; i -= 3145728u; }
    else if (i < 3670016u){ src = wv; dst = g_wqkvh + 2621440u; i -= 3407872u; }
    else                  { src = wo; dst = g_woh;              i -= 3670016u; }
    float4 v = ((const float4*)src)[i];
    dst[2*i]   = f2h2(v.x, v.y);
    dst[2*i+1] = f2h2(v.z, v.w);
}

// ---------------- half GEMM: C[M,N] = A[M,K] @ W[N,K]^T ---------------------
// Block tile 128x128, k-step 64 halves, 3-stage cp.async pipeline with ONE
// __syncthreads per k-tile, ldmatrix fragments, 8 warps (2m x 4n).
// MODE 0: fused QKV epilogue; MODE 1: plain f32 C (O-projection).
#define GH_ROWB 144u                 // 64 halves + 8 pad = 144 bytes/row
#define GH_TILE (128u*GH_ROWB)       // 18432 B per operand tile
#define GH_BUF  (2u*GH_TILE)         // A+B per stage
#define GH_SMEM (3*GH_BUF)           // 110592 B (3 stages)

template<int MODE>
__global__ void __launch_bounds__(256,2) gemm_h(const uint32_t* __restrict__ A,
                                                const uint32_t* __restrict__ W,
                                                float* __restrict__ C,
                                                const float* __restrict__ cs,
                                                const float* __restrict__ sn,
                                                int N, int K)
{
    extern __shared__ char smem[];
    const uint32_t sb = (uint32_t)__cvta_generic_to_shared(smem);
    const int tid  = threadIdx.x;
    const int warp = tid >> 5, lane = tid & 31;
    const int g = lane >> 2, t = lane & 3;
    const int wm = warp & 1, wn = warp >> 1;
    const int m0 = blockIdx.y * 128, n0 = blockIdx.x * 128;
    const int KW = K >> 1;                         // half2 words per row

    const uint32_t* Ag = A + (size_t)m0 * KW;
    const uint32_t* Wg = W + (size_t)n0 * KW;

    float acc[4][4][4];
    #pragma unroll
    for (int a=0;a<4;a++)
        #pragma unroll
        for (int b2=0;b2<4;b2++)
            #pragma unroll
            for (int c=0;c<4;c++) acc[a][b2][c]=0.f;

    // per-thread cp.async map: 4 (row,chunk) pairs per operand
    int crow[4], cch[4];
    #pragma unroll
    for (int j=0;j<4;j++){ int idx = tid + j*256; crow[j]=idx>>3; cch[j]=idx&7; }

    auto load_tile = [&](int buf, int ktw){
        uint32_t sA = sb + buf*GH_BUF;
        uint32_t sB = sA + GH_TILE;
        #pragma unroll
        for (int j=0;j<4;j++){
            uint32_t off = crow[j]*GH_ROWB + cch[j]*16;
            const uint32_t* ga = Ag + (size_t)crow[j]*KW + ktw + cch[j]*4;
            const uint32_t* gb = Wg + (size_t)crow[j]*KW + ktw + cch[j]*4;
            CP_ASYNC16(sA + off, ga);
            CP_ASYNC16(sB + off, gb);
        }
    };

    const int NT = KW / 32;                        // k64-half tiles
    load_tile(0, 0); CP_COMMIT();
    if (NT > 1){ load_tile(1, 32); CP_COMMIT(); }

    const int selA = lane >> 3, lr = lane & 7;
    for (int s2 = 0; s2 < NT; s2++){
        const int buf = s2 % 3;
        if (s2 + 1 < NT) CP_WAIT1(); else CP_WAIT0();
        __syncthreads();                           // single barrier per k-tile
        if (s2 + 2 < NT){ load_tile((s2+2)%3, (s2+2)*32); CP_COMMIT(); }

        uint32_t sA = sb + buf*GH_BUF + (wm*64)*GH_ROWB;
        uint32_t sB = sb + buf*GH_BUF + GH_TILE + (wn*32)*GH_ROWB;
        #pragma unroll
        for (int kg = 0; kg < 4; kg++){
            uint32_t af[4][4], bf[4][2];
            #pragma unroll
            for (int mi=0; mi<4; mi++){
                uint32_t addr = sA + (mi*16 + (selA&1)*8 + lr)*GH_ROWB
                                   + (kg*16 + (selA>>1)*8)*2;
                ldmx4(af[mi], addr);
            }
            #pragma unroll
            for (int np=0; np<2; np++){
                uint32_t r[4];
                uint32_t addr = sB + (np*16 + (selA>>1)*8 + lr)*GH_ROWB
                                   + (kg*16 + (selA&1)*8)*2;
                ldmx4(r, addr);
                bf[np*2  ][0]=r[0]; bf[np*2  ][1]=r[1];
                bf[np*2+1][0]=r[2]; bf[np*2+1][1]=r[3];
            }
            #pragma unroll
            for (int mi=0; mi<4; mi++)
                #pragma unroll
                for (int ni=0; ni<4; ni++)
                    mma16(acc[mi][ni], af[mi], bf[ni]);
        }
    }

    // ---------------- fused epilogues ---------------------------------------
    const float qs = 0.08838834764831845f;         // 1/sqrt(128)
    const int region = (MODE == 0) ? ((blockIdx.x < 16) ? 0 : (blockIdx.x < 20) ? 1 : 2) : 3;
    #pragma unroll
    for (int mi=0; mi<4; mi++){
        int r  = m0 + wm*64 + mi*16 + g;
        int r2 = r + 8;
        if (MODE == 1){
            #pragma unroll
            for (int ni=0; ni<4; ni++){
                int c = n0 + wn*32 + ni*8 + 2*t;
                *(float2*)(C + (size_t)r *N + c) = make_float2(acc[mi][ni][0], acc[mi][ni][1]);
                *(float2*)(C + (size_t)r2*N + c) = make_float2(acc[mi][ni][2], acc[mi][ni][3]);
            }
        } else {
            int b0 = r >> 11,  s0 = r  & (SS-1);
            int b1 = r2 >> 11, s1 = r2 & (SS-1);
            #pragma unroll
            for (int ni=0; ni<4; ni++){
                int c = n0 + wn*32 + ni*8 + 2*t;
                float a0=acc[mi][ni][0], a1=acc[mi][ni][1];
                float a2=acc[mi][ni][2], a3=acc[mi][ni][3];
                if (region == 0){                  // Q: rope + scale
                    int h = c >> 7, i = (c & 127) >> 1;
                    float cv0=cs[s0*64+i], sv0=sn[s0*64+i];
                    float cv1=cs[s1*64+i], sv1=sn[s1*64+i];
                    g_QtW[((size_t)(b0*HH+h)*SS + s0)*64 + i] =
                        f2h2((a0*cv0 - a1*sv0)*qs, (a0*sv0 + a1*cv0)*qs);
                    g_QtW[((size_t)(b1*HH+h)*SS + s1)*64 + i] =
                        f2h2((a2*cv1 - a3*sv1)*qs, (a2*sv1 + a3*cv1)*qs);
                } else if (region == 1){           // K: rope
                    int ck = c - 2048;
                    int h = ck >> 7, i = (ck & 127) >> 1;
                    float cv0=cs[s0*64+i], sv0=sn[s0*64+i];
                    float cv1=cs[s1*64+i], sv1=sn[s1*64+i];
                    g_KtW[((size_t)(b0*KVH+h)*SS + s0)*64 + i] =
                        f2h2(a0*cv0 - a1*sv0, a0*sv0 + a1*cv0);
                    g_KtW[((size_t)(b1*KVH+h)*SS + s1)*64 + i] =
                        f2h2(a2*cv1 - a3*sv1, a2*sv1 + a3*cv1);
                } else {                           // V: transpose only
                    int cv = c - 2560;
                    int h = cv >> 7, i = (cv & 127) >> 1;
                    g_VtW[((size_t)(b0*KVH+h)*SS + s0)*64 + i] = f2h2(a0, a1);
                    g_VtW[((size_t)(b1*KVH+h)*SS + s1)*64 + i] = f2h2(a2, a3);
                }
            }
        }
    }
}

// ---------------- tensor-core flash attention (f16 mma, causal) -------------
// grid: (32 q-tiles heaviest-first, B*H=32); 256 thr = 8 warps.
// K/V tiles double-buffered via cp.async; prefetch of tile kti+1 issues after
// the mid-softmax barrier (all warps provably inside iter kti => buf^1 dead).
#define FQ_OFF  0          // Qs [64][68] half2 words (Q pre-scaled)
#define FK_OFF  4352       // Ks[2] each 64*68
#define FV_OFF  13056      // Vs[2] each 64*68
#define FP_OFF  21760      // Ps [64][36] half2 prob words
#define FRM_OFF 24064      // RedM [2][64] float
#define FRS_OFF 24192      // RedS [2][64] float
#define FLASH_SMEM (24320*4)

__global__ void __launch_bounds__(256,2) flash_f16_kernel(){
    extern __shared__ uint32_t sm[];
    uint32_t* Qs = sm + FQ_OFF;
    uint32_t* Ps = sm + FP_OFF;
    float* RedM = (float*)(sm + FRM_OFF);
    float* RedS = (float*)(sm + FRS_OFF);
    const uint32_t sbB = (uint32_t)__cvta_generic_to_shared(sm);

    const int qt = 31 - blockIdx.x;          // heaviest tiles first
    const int bh = blockIdx.y;
    const int b = bh >> 4, h = bh & 15;
    const int kvh = h >> 2;
    const int q0 = qt * 64;
    const int tid = threadIdx.x;
    const int lane = tid & 31;
    const int g = lane >> 2, t = lane & 3;
    const int wm = (tid >> 5) & 3, wn = tid >> 7;
    const int r0 = wm * 16;

    const uint32_t* Qg = g_QtW + (size_t)(b*HH + h)   * SS * 64;
    const uint32_t* Kg = g_KtW + (size_t)(b*KVH + kvh)* SS * 64;
    const uint32_t* Vg = g_VtW + (size_t)(b*KVH + kvh)* SS * 64;

    // async K+V tile load into buffer `buf` (2048 16B chunks, 8/thread)
    auto ldkv = [&](int k0, int buf){
        uint32_t kb = sbB + (FK_OFF + buf*4352)*4;
        uint32_t vb = sbB + (FV_OFF + buf*4352)*4;
        #pragma unroll
        for (int j = 0; j < 8; j++){
            int i = tid + j*256;
            int op = i >> 10, rem = i & 1023, r = rem >> 4, ch = rem & 15;
            const uint32_t* src = (op ? Vg : Kg) + (size_t)(k0+r)*64 + ch*4;
            uint32_t dst = (op ? vb : kb) + (uint32_t)(r*272 + ch*16);
            CP_ASYNC16(dst, src);
        }
    };

    for (int i = tid; i < 64*16; i += 256) {       // Q: 64 rows x 16 uint4
        int r = i >> 4, w4 = (i & 15) * 4;
        *(uint4*)(Qs + r*68 + w4) = *(const uint4*)(Qg + (size_t)(q0+r)*64 + w4);
    }
    ldkv(0, 0); CP_COMMIT();

    float O[8][4];
    #pragma unroll
    for (int ni=0;ni<8;ni++)
        #pragma unroll
        for (int j=0;j<4;j++) O[ni][j]=0.f;
    float m_r[2] = {-INFINITY,-INFINITY};
    float l_r[2] = {0.f,0.f};

    for (int kti = 0; kti <= qt; kti++) {
        int k0 = kti * 64;
        const int buf = kti & 1;
        uint32_t* Ks = sm + FK_OFF + buf*4352;
        uint32_t* Vs = sm + FV_OFF + buf*4352;
        const uint32_t vbase = sbB + (FV_OFF + buf*4352)*4;

        CP_WAIT0();
        __syncthreads();                          // tile visible to all warps

        // ---- S = Q @ K^T (f16 mma, k = HD = 8 groups of 16) --------------
        float sc[4][4];
        #pragma unroll
        for (int ni=0;ni<4;ni++)
            #pragma unroll
            for (int j=0;j<4;j++) sc[ni][j]=0.f;
        #pragma unroll
        for (int ks = 0; ks < 8; ks++) {
            int base = ks * 8;                     // word offset of k16 group
            uint32_t a[4];
            a[0]=Qs[(r0+g  )*68 + base+t  ];
            a[1]=Qs[(r0+g+8)*68 + base+t  ];
            a[2]=Qs[(r0+g  )*68 + base+t+4];
            a[3]=Qs[(r0+g+8)*68 + base+t+4];
            #pragma unroll
            for (int ni=0;ni<4;ni++){
                int n = wn*32 + ni*8 + g;
                uint32_t bfr[2];
                bfr[0]=Ks[n*68 + base+t  ];
                bfr[1]=Ks[n*68 + base+t+4];
                mma16(sc[ni], a, bfr);
            }
        }

        if (kti == qt) {                          // causal mask on diagonal
            int rg0 = q0 + r0 + g, rg1 = rg0 + 8;
            #pragma unroll
            for (int ni=0;ni<4;ni++){
                int ck = k0 + wn*32 + ni*8 + 2*t;
                if (ck   > rg0) sc[ni][0] = -INFINITY;
                if (ck+1 > rg0) sc[ni][1] = -INFINITY;
                if (ck   > rg1) sc[ni][2] = -INFINITY;
                if (ck+1 > rg1) sc[ni][3] = -INFINITY;
            }
        }

        // ---- online softmax on fragments --------------------------------
        float mx0 = -INFINITY, mx1 = -INFINITY;
        #pragma unroll
        for (int ni=0;ni<4;ni++){
            mx0 = fmaxf(mx0, fmaxf(sc[ni][0], sc[ni][1]));
            mx1 = fmaxf(mx1, fmaxf(sc[ni][2], sc[ni][3]));
        }
        mx0 = fmaxf(mx0, __shfl_xor_sync(0xffffffffu, mx0, 1));
        mx0 = fmaxf(mx0, __shfl_xor_sync(0xffffffffu, mx0, 2));
        mx1 = fmaxf(mx1, __shfl_xor_sync(0xffffffffu, mx1, 1));
        mx1 = fmaxf(mx1, __shfl_xor_sync(0xffffffffu, mx1, 2));
        if (t == 0) {
            RedM[wn*64 + r0+g  ] = mx0;
            RedM[wn*64 + r0+g+8] = mx1;
        }
        __syncthreads();
        float mt0 = fmaxf(RedM[r0+g  ], RedM[64 + r0+g  ]);
        float mt1 = fmaxf(RedM[r0+g+8], RedM[64 + r0+g+8]);
        float mn0 = fmaxf(m_r[0], mt0), mn1 = fmaxf(m_r[1], mt1);
        float f0 = __expf(m_r[0] - mn0), f1 = __expf(m_r[1] - mn1);
        m_r[0] = mn0; m_r[1] = mn1;

        float s0 = 0.f, s1 = 0.f;
        #pragma unroll
        for (int ni=0;ni<4;ni++){
            float p0 = __expf(sc[ni][0] - mn0);
            float p1 = __expf(sc[ni][1] - mn0);
            float p2 = __expf(sc[ni][2] - mn1);
            float p3 = __expf(sc[ni][3] - mn1);
            s0 += p0 + p1; s1 += p2 + p3;
            int w = wn*16 + ni*4 + t;             // word = col/2
            Ps[(r0+g  )*36 + w] = f2h2(p0, p1);
            Ps[(r0+g+8)*36 + w] = f2h2(p2, p3);
        }
        s0 += __shfl_xor_sync(0xffffffffu, s0, 1);
        s0 += __shfl_xor_sync(0xffffffffu, s0, 2);
        s1 += __shfl_xor_sync(0xffffffffu, s1, 1);
        s1 += __shfl_xor_sync(0xffffffffu, s1, 2);
        if (t == 0) {
            RedS[wn*64 + r0+g  ] = s0;
            RedS[wn*64 + r0+g+8] = s1;
        }
        #pragma unroll
        for (int ni=0;ni<8;ni++){
            O[ni][0] *= f0; O[ni][1] *= f0;
            O[ni][2] *= f1; O[ni][3] *= f1;
        }
        __syncthreads();                          // Ps + sums visible; all warps in iter kti
        l_r[0] = l_r[0]*f0 + RedS[r0+g  ] + RedS[64 + r0+g  ];
        l_r[1] = l_r[1]*f1 + RedS[r0+g+8] + RedS[64 + r0+g+8];

        // prefetch next K/V tile into the dead buffer (overlaps with PV)
        if (kti + 1 <= qt){ ldkv(k0 + 64, buf ^ 1); CP_COMMIT(); }

        // ---- O += P @ V (f16 mma; V B-frags via ldmatrix.trans) ----------
        #pragma unroll
        for (int ks = 0; ks < 4; ks++) {          // 64 kseq = 4 groups of 16
            int base = ks * 8;
            uint32_t a[4];
            a[0]=Ps[(r0+g  )*36 + base+t  ];
            a[1]=Ps[(r0+g+8)*36 + base+t  ];
            a[2]=Ps[(r0+g  )*36 + base+t+4];
            a[3]=Ps[(r0+g+8)*36 + base+t+4];
            #pragma unroll
            for (int p = 0; p < 4; p++) {         // d16 pair -> ni 2p, 2p+1
                uint32_t b0,b1,b2,b3;
                uint32_t addr = vbase
                    + (uint32_t)((ks*16 + (lane & 15)) * 272        // row k: 68 words
                    + (wn*64 + p*16 + ((lane >> 4) << 3)) * 2);     // col d in halves
                asm volatile(
                    "ldmatrix.sync.aligned.m8n8.x4.trans.shared.b16 {%0,%1,%2,%3}, [%4];"
                    : "=r"(b0),"=r"(b1),"=r"(b2),"=r"(b3) : "r"(addr));
                uint32_t bb0[2]={b0,b1}, bb1[2]={b2,b3};
                mma16(O[2*p],   a, bb0);
                mma16(O[2*p+1], a, bb1);
            }
        }
    }

    float inv0 = 1.f / l_r[0], inv1 = 1.f / l_r[1];
    int rg0 = q0 + r0 + g, rg1 = rg0 + 8;
    #pragma unroll
    for (int ni=0;ni<8;ni++){
        int c = h*HD + wn*64 + ni*8 + 2*t;        // even
        int cw = c >> 1;
        g_AttOh[((size_t)(b*SS)+rg0)*(DD/2) + cw] = f2h2(O[ni][0]*inv0, O[ni][1]*inv0);
        g_AttOh[((size_t)(b*SS)+rg1)*(DD/2) + cw] = f2h2(O[ni][2]*inv1, O[ni][3]*inv1);
    }
}

// ---------------- launch ----------------------------------------------------
extern "C" void kernel_launch(void* const* d_in, const int* in_sizes, int n_in,
                              void* d_out, int out_size){
    const float* x  = (const float*)d_in[0];
    const float* fc = (const float*)d_in[1];
    const float* fs = (const float*)d_in[2];
    const float* wq = (const float*)d_in[3];
    const float* wk = (const float*)d_in[4];
    const float* wv = (const float*)d_in[5];
    const float* wo = (const float*)d_in[6];
    float* out = (float*)d_out;

    uint32_t *pxh, *pwqkvh, *pwoh, *pAoh;
    cudaGetSymbolAddress((void**)&pxh,    g_xh);
    cudaGetSymbolAddress((void**)&pwqkvh, g_wqkvh);
    cudaGetSymbolAddress((void**)&pwoh,   g_woh);
    cudaGetSymbolAddress((void**)&pAoh,   g_AttOh);

    cudaFuncSetAttribute(gemm_h<0>, cudaFuncAttributeMaxDynamicSharedMemorySize, GH_SMEM);
    cudaFuncSetAttribute(gemm_h<1>, cudaFuncAttributeMaxDynamicSharedMemorySize, GH_SMEM);
    cudaFuncSetAttribute(flash_f16_kernel,
        cudaFuncAttributeMaxDynamicSharedMemorySize, FLASH_SMEM);

    cvt_kernel<<<18432, 256>>>(x, wq, wk, wv, wo);                              // 0
    gemm_h<0><<<dim3(24,32),256,GH_SMEM>>>(pxh, pwqkvh, nullptr, fc, fs, NQKV, 2048); // 1
    flash_f16_kernel<<<dim3(32,32),256,FLASH_SMEM>>>();                         // 2
    gemm_h<1><<<dim3(16,32),256,GH_SMEM>>>(pAoh, pwoh, out, nullptr, nullptr, 2048, 2048); // 3
}

// round 13
// speedup vs baseline: 1.4961x; 1.4961x over previous
#include <cuda_runtime.h>
#include <cuda_fp16.h>
#include <math.h>
#include <stdint.h>

#define BB 2
#define SS 2048
#define DD 2048
#define HH 16
#define KVH 4
#define HD 128
#define MM (BB*SS)        // 4096 rows
#define KVD (KVH*HD)      // 512
#define NQKV (DD + 2*KVD) // 3072 stacked rows

// ---------------- scratch (device globals; no allocation allowed) ----------
__device__ uint32_t g_xh   [(size_t)MM*DD/2];     // x as half2 words
__device__ uint32_t g_wqkvh[(size_t)NQKV*DD/2];   // wq|wk|wv stacked, half2
__device__ uint32_t g_woh  [(size_t)DD*DD/2];
__device__ uint32_t g_QtW[(size_t)MM*DD/2];       // roped+scaled Q [b,h,s,d] half2
__device__ uint32_t g_KtW[(size_t)MM*KVD/2];      // roped K        [b,kh,s,d]
__device__ uint32_t g_VtW[(size_t)MM*KVD/2];      // V              [b,kh,s,d]
__device__ uint32_t g_AttOh[(size_t)MM*DD/2];     // attention out  [b,s,h*d] half2

// ---------------- helpers ----------------------------------------------------
__device__ __forceinline__ uint32_t f2h2(float x, float y){
    __half2 h = __floats2half2_rn(x, y);       // .x = low = first elem
    return *(uint32_t*)&h;
}
__device__ __forceinline__ void mma16(float* c, const uint32_t* a, const uint32_t* b){
    asm volatile("mma.sync.aligned.m16n8k16.row.col.f32.f16.f16.f32 "
        "{%0,%1,%2,%3}, {%4,%5,%6,%7}, {%8,%9}, {%0,%1,%2,%3};"
        : "+f"(c[0]),"+f"(c[1]),"+f"(c[2]),"+f"(c[3])
        : "r"(a[0]),"r"(a[1]),"r"(a[2]),"r"(a[3]),"r"(b[0]),"r"(b[1]));
}
__device__ __forceinline__ void ldmx4(uint32_t* r, uint32_t addr){
    asm volatile("ldmatrix.sync.aligned.m8n8.x4.shared.b16 {%0,%1,%2,%3}, [%4];"
        : "=r"(r[0]),"=r"(r[1]),"=r"(r[2]),"=r"(r[3]) : "r"(addr));
}
#define CP_ASYNC16(dst, src) \
    asm volatile("cp.async.cg.shared.global [%0], [%1], 16;" :: "r"(dst), "l"(src))
#define CP_COMMIT() asm volatile("cp.async.commit_group;")
#define CP_WAIT1()  asm volatile("cp.async.wait_group 1;" ::: "memory")
#define CP_WAIT0()  asm volatile("cp.async.wait_group 0;" ::: "memory")

// ---------------- fp32 -> fp16 conversion prep -------------------------------
// float4-granular. wq/wk/wv stack into g_wqkvh (rows 0-2047 | 2048-2559 | 2560-3071)
__global__ void cvt_kernel(const float* __restrict__ x,  const float* __restrict__ wq,
                           const float* __restrict__ wk, const float* __restrict__ wv,
                           const float* __restrict__ wo){
    size_t i = (size_t)blockIdx.x*256 + threadIdx.x;   // float4 index
    const float* src; uint32_t* dst;
    if      (i < 2097152u){ src = x;  dst = g_xh;                              }
    else if (i < 3145728u){ src = wq; dst = g_wqkvh;            i -= 2097152u; }
    else if (i < 3407872u){ src = wk; dst = g_wqkvh + 2097152u; i -= 3145728u; }
    else if (i < 3670016u){ src = wv; dst = g_wqkvh + 2621440u; i -= 3407872u; }
    else                  { src = wo; dst = g_woh;              i -= 3670016u; }
    float4 v = ((const float4*)src)[i];
    dst[2*i]   = f2h2(v.x, v.y);
    dst[2*i+1] = f2h2(v.z, v.w);
}

// ---------------- half GEMM: C[M,N] = A[M,K] @ W[N,K]^T ---------------------
// Block tile 128x128, k-step 64 halves, cp.async double buffer (R11 skeleton:
// load issue in the wait shadow, two barriers per k-tile), ldmatrix fragments
// SOFTWARE-PIPELINED (double-buffered regs: load kg+1 while mma kg).
// MODE 0: fused QKV epilogue; MODE 1: plain f32 C (O-projection).
#define GH_ROWB 144u                 // 64 halves + 8 pad = 144 bytes/row
#define GH_TILE (128u*GH_ROWB)       // 18432 B per operand tile
#define GH_BUF  (2u*GH_TILE)         // A+B per buffer
#define GH_SMEM (2*GH_BUF)           // 73728 B

template<int MODE>
__global__ void __launch_bounds__(256,2) gemm_h(const uint32_t* __restrict__ A,
                                                const uint32_t* __restrict__ W,
                                                float* __restrict__ C,
                                                const float* __restrict__ cs,
                                                const float* __restrict__ sn,
                                                int N, int K)
{
    extern __shared__ char smem[];
    const uint32_t sb = (uint32_t)__cvta_generic_to_shared(smem);
    const int tid  = threadIdx.x;
    const int warp = tid >> 5, lane = tid & 31;
    const int g = lane >> 2, t = lane & 3;
    const int wm = warp & 1, wn = warp >> 1;
    const int m0 = blockIdx.y * 128, n0 = blockIdx.x * 128;
    const int KW = K >> 1;                         // half2 words per row

    const uint32_t* Ag = A + (size_t)m0 * KW;
    const uint32_t* Wg = W + (size_t)n0 * KW;

    float acc[4][4][4];
    #pragma unroll
    for (int a=0;a<4;a++)
        #pragma unroll
        for (int b2=0;b2<4;b2++)
            #pragma unroll
            for (int c=0;c<4;c++) acc[a][b2][c]=0.f;

    // per-thread cp.async map: 4 (row,chunk) pairs per operand
    int crow[4], cch[4];
    #pragma unroll
    for (int j=0;j<4;j++){ int idx = tid + j*256; crow[j]=idx>>3; cch[j]=idx&7; }

    auto load_tile = [&](int buf, int ktw){
        uint32_t sA = sb + buf*GH_BUF;
        uint32_t sB = sA + GH_TILE;
        #pragma unroll
        for (int j=0;j<4;j++){
            uint32_t off = crow[j]*GH_ROWB + cch[j]*16;
            const uint32_t* ga = Ag + (size_t)crow[j]*KW + ktw + cch[j]*4;
            const uint32_t* gb = Wg + (size_t)crow[j]*KW + ktw + cch[j]*4;
            CP_ASYNC16(sA + off, ga);
            CP_ASYNC16(sB + off, gb);
        }
    };

    const int NT = KW / 32;                        // k64-half tiles
    load_tile(0, 0); CP_COMMIT();

    const int selA = lane >> 3, lr = lane & 7;
    for (int s2 = 0; s2 < NT; s2++){
        const int buf = s2 & 1;
        if (s2 + 1 < NT){ load_tile(buf^1, (s2+1)*32); CP_COMMIT(); CP_WAIT1(); }
        else            { CP_WAIT0(); }
        __syncthreads();

        uint32_t sA = sb + buf*GH_BUF + (wm*64)*GH_ROWB;
        uint32_t sB = sb + buf*GH_BUF + GH_TILE + (wn*32)*GH_ROWB;

        // fragment double-buffer: load kg+1 while issuing kg's MMAs
        uint32_t af[2][4][4], bf[2][4][2];
        auto ldfrag = [&](int kg, int pb){
            #pragma unroll
            for (int mi=0; mi<4; mi++){
                uint32_t addr = sA + (mi*16 + (selA&1)*8 + lr)*GH_ROWB
                                   + (kg*16 + (selA>>1)*8)*2;
                ldmx4(af[pb][mi], addr);
            }
            #pragma unroll
            for (int np=0; np<2; np++){
                uint32_t r[4];
                uint32_t addr = sB + (np*16 + (selA>>1)*8 + lr)*GH_ROWB
                                   + (kg*16 + (selA&1)*8)*2;
                ldmx4(r, addr);
                bf[pb][np*2  ][0]=r[0]; bf[pb][np*2  ][1]=r[1];
                bf[pb][np*2+1][0]=r[2]; bf[pb][np*2+1][1]=r[3];
            }
        };
        ldfrag(0, 0);
        #pragma unroll
        for (int kg = 0; kg < 4; kg++){
            const int pb = kg & 1;
            if (kg < 3) ldfrag(kg+1, pb^1);
            #pragma unroll
            for (int mi=0; mi<4; mi++)
                #pragma unroll
                for (int ni=0; ni<4; ni++)
                    mma16(acc[mi][ni], af[pb][mi], bf[pb][ni]);
        }
        __syncthreads();
    }

    // ---------------- fused epilogues ---------------------------------------
    const float qs = 0.08838834764831845f;         // 1/sqrt(128)
    const int region = (MODE == 0) ? ((blockIdx.x < 16) ? 0 : (blockIdx.x < 20) ? 1 : 2) : 3;
    #pragma unroll
    for (int mi=0; mi<4; mi++){
        int r  = m0 + wm*64 + mi*16 + g;
        int r2 = r + 8;
        if (MODE == 1){
            #pragma unroll
            for (int ni=0; ni<4; ni++){
                int c = n0 + wn*32 + ni*8 + 2*t;
                *(float2*)(C + (size_t)r *N + c) = make_float2(acc[mi][ni][0], acc[mi][ni][1]);
                *(float2*)(C + (size_t)r2*N + c) = make_float2(acc[mi][ni][2], acc[mi][ni][3]);
            }
        } else {
            int b0 = r >> 11,  s0 = r  & (SS-1);
            int b1 = r2 >> 11, s1 = r2 & (SS-1);
            #pragma unroll
            for (int ni=0; ni<4; ni++){
                int c = n0 + wn*32 + ni*8 + 2*t;
                float a0=acc[mi][ni][0], a1=acc[mi][ni][1];
                float a2=acc[mi][ni][2], a3=acc[mi][ni][3];
                if (region == 0){                  // Q: rope + scale
                    int h = c >> 7, i = (c & 127) >> 1;
                    float cv0=cs[s0*64+i], sv0=sn[s0*64+i];
                    float cv1=cs[s1*64+i], sv1=sn[s1*64+i];
                    g_QtW[((size_t)(b0*HH+h)*SS + s0)*64 + i] =
                        f2h2((a0*cv0 - a1*sv0)*qs, (a0*sv0 + a1*cv0)*qs);
                    g_QtW[((size_t)(b1*HH+h)*SS + s1)*64 + i] =
                        f2h2((a2*cv1 - a3*sv1)*qs, (a2*sv1 + a3*cv1)*qs);
                } else if (region == 1){           // K: rope
                    int ck = c - 2048;
                    int h = ck >> 7, i = (ck & 127) >> 1;
                    float cv0=cs[s0*64+i], sv0=sn[s0*64+i];
                    float cv1=cs[s1*64+i], sv1=sn[s1*64+i];
                    g_KtW[((size_t)(b0*KVH+h)*SS + s0)*64 + i] =
                        f2h2(a0*cv0 - a1*sv0, a0*sv0 + a1*cv0);
                    g_KtW[((size_t)(b1*KVH+h)*SS + s1)*64 + i] =
                        f2h2(a2*cv1 - a3*sv1, a2*sv1 + a3*cv1);
                } else {                           // V: transpose only
                    int cv = c - 2560;
                    int h = cv >> 7, i = (cv & 127) >> 1;
                    g_VtW[((size_t)(b0*KVH+h)*SS + s0)*64 + i] = f2h2(a0, a1);
                    g_VtW[((size_t)(b1*KVH+h)*SS + s1)*64 + i] = f2h2(a2, a3);
                }
            }
        }
    }
}

// ---------------- tensor-core flash attention (f16 mma, causal) -------------
// R11 version (proven 508us): synchronous K/V tile loads, single smem buffer.
#define FQ_OFF 0          // Qs [64][68] half2 words (Q pre-scaled)
#define FK_OFF 4352       // Ks [64][68]
#define FV_OFF 8704       // Vs [64][68]  row-major [k][d] (ldmatrix.trans source)
#define FP_OFF 13056      // Ps [64][36]  half2 prob words
#define FRM_OFF 15360     // RedM [2][64] float
#define FRS_OFF 15488     // RedS [2][64] float
#define FLASH_SMEM (15616*4)

__global__ void __launch_bounds__(256) flash_f16_kernel(){
    extern __shared__ uint32_t sm[];
    uint32_t* Qs = sm + FQ_OFF;
    uint32_t* Ks = sm + FK_OFF;
    uint32_t* Vs = sm + FV_OFF;
    uint32_t* Ps = sm + FP_OFF;
    float* RedM = (float*)(sm + FRM_OFF);
    float* RedS = (float*)(sm + FRS_OFF);
    const uint32_t vbase = (uint32_t)__cvta_generic_to_shared(Vs);

    const int qt = 31 - blockIdx.x;          // heaviest tiles first
    const int bh = blockIdx.y;
    const int b = bh >> 4, h = bh & 15;
    const int kvh = h >> 2;
    const int q0 = qt * 64;
    const int tid = threadIdx.x;
    const int warp = tid >> 5, lane = tid & 31;
    const int g = lane >> 2, t = lane & 3;
    const int wm = warp & 3, wn = warp >> 2;
    const int r0 = wm * 16;

    const uint32_t* Qg = g_QtW + (size_t)(b*HH + h)   * SS * 64;
    const uint32_t* Kg = g_KtW + (size_t)(b*KVH + kvh)* SS * 64;
    const uint32_t* Vg = g_VtW + (size_t)(b*KVH + kvh)* SS * 64;

    for (int i = tid; i < 64*16; i += 256) {       // Q: 64 rows x 16 uint4
        int r = i >> 4, w4 = (i & 15) * 4;
        *(uint4*)(Qs + r*68 + w4) = *(const uint4*)(Qg + (size_t)(q0+r)*64 + w4);
    }

    float O[8][4];
    #pragma unroll
    for (int ni=0;ni<8;ni++)
        #pragma unroll
        for (int j=0;j<4;j++) O[ni][j]=0.f;
    float m_r[2] = {-INFINITY,-INFINITY};
    float l_r[2] = {0.f,0.f};

    for (int kti = 0; kti <= qt; kti++) {
        int k0 = kti * 64;
        __syncthreads();                          // prev consumers done with Ks/Vs
        for (int i = tid; i < 64*16; i += 256) {
            int r = i >> 4, w4 = (i & 15) * 4;
            *(uint4*)(Ks + r*68 + w4) = *(const uint4*)(Kg + (size_t)(k0+r)*64 + w4);
            *(uint4*)(Vs + r*68 + w4) = *(const uint4*)(Vg + (size_t)(k0+r)*64 + w4);
        }
        __syncthreads();

        // ---- S = Q @ K^T (f16 mma, k = HD = 8 groups of 16) --------------
        float sc[4][4];
        #pragma unroll
        for (int ni=0;ni<4;ni++)
            #pragma unroll
            for (int j=0;j<4;j++) sc[ni][j]=0.f;
        #pragma unroll
        for (int ks = 0; ks < 8; ks++) {
            int base = ks * 8;                     // word offset of k16 group
            uint32_t a[4];
            a[0]=Qs[(r0+g  )*68 + base+t  ];
            a[1]=Qs[(r0+g+8)*68 + base+t  ];
            a[2]=Qs[(r0+g  )*68 + base+t+4];
            a[3]=Qs[(r0+g+8)*68 + base+t+4];
            #pragma unroll
            for (int ni=0;ni<4;ni++){
                int n = wn*32 + ni*8 + g;
                uint32_t bfr[2];
                bfr[0]=Ks[n*68 + base+t  ];
                bfr[1]=Ks[n*68 + base+t+4];
                mma16(sc[ni], a, bfr);
            }
        }

        if (kti == qt) {                          // causal mask on diagonal
            int rg0 = q0 + r0 + g, rg1 = rg0 + 8;
            #pragma unroll
            for (int ni=0;ni<4;ni++){
                int ck = k0 + wn*32 + ni*8 + 2*t;
                if (ck   > rg0) sc[ni][0] = -INFINITY;
                if (ck+1 > rg0) sc[ni][1] = -INFINITY;
                if (ck   > rg1) sc[ni][2] = -INFINITY;
                if (ck+1 > rg1) sc[ni][3] = -INFINITY;
            }
        }

        // ---- online softmax on fragments --------------------------------
        float mx0 = -INFINITY, mx1 = -INFINITY;
        #pragma unroll
        for (int ni=0;ni<4;ni++){
            mx0 = fmaxf(mx0, fmaxf(sc[ni][0], sc[ni][1]));
            mx1 = fmaxf(mx1, fmaxf(sc[ni][2], sc[ni][3]));
        }
        mx0 = fmaxf(mx0, __shfl_xor_sync(0xffffffffu, mx0, 1));
        mx0 = fmaxf(mx0, __shfl_xor_sync(0xffffffffu, mx0, 2));
        mx1 = fmaxf(mx1, __shfl_xor_sync(0xffffffffu, mx1, 1));
        mx1 = fmaxf(mx1, __shfl_xor_sync(0xffffffffu, mx1, 2));
        if (t == 0) {
            RedM[wn*64 + r0+g  ] = mx0;
            RedM[wn*64 + r0+g+8] = mx1;
        }
        __syncthreads();
        float mt0 = fmaxf(RedM[r0+g  ], RedM[64 + r0+g  ]);
        float mt1 = fmaxf(RedM[r0+g+8], RedM[64 + r0+g+8]);
        float mn0 = fmaxf(m_r[0], mt0), mn1 = fmaxf(m_r[1], mt1);
        float f0 = __expf(m_r[0] - mn0), f1 = __expf(m_r[1] - mn1);
        m_r[0] = mn0; m_r[1] = mn1;

        float s0 = 0.f, s1 = 0.f;
        #pragma unroll
        for (int ni=0;ni<4;ni++){
            float p0 = __expf(sc[ni][0] - mn0);
            float p1 = __expf(sc[ni][1] - mn0);
            float p2 = __expf(sc[ni][2] - mn1);
            float p3 = __expf(sc[ni][3] - mn1);
            s0 += p0 + p1; s1 += p2 + p3;
            int w = wn*16 + ni*4 + t;             // word = col/2
            Ps[(r0+g  )*36 + w] = f2h2(p0, p1);
            Ps[(r0+g+8)*36 + w] = f2h2(p2, p3);
        }
        s0 += __shfl_xor_sync(0xffffffffu, s0, 1);
        s0 += __shfl_xor_sync(0xffffffffu, s0, 2);
        s1 += __shfl_xor_sync(0xffffffffu, s1, 1);
        s1 += __shfl_xor_sync(0xffffffffu, s1, 2);
        if (t == 0) {
            RedS[wn*64 + r0+g  ] = s0;
            RedS[wn*64 + r0+g+8] = s1;
        }
        #pragma unroll
        for (int ni=0;ni<8;ni++){
            O[ni][0] *= f0; O[ni][1] *= f0;
            O[ni][2] *= f1; O[ni][3] *= f1;
        }
        __syncthreads();                          // Ps + sums visible
        l_r[0] = l_r[0]*f0 + RedS[r0+g  ] + RedS[64 + r0+g  ];
        l_r[1] = l_r[1]*f1 + RedS[r0+g+8] + RedS[64 + r0+g+8];

        // ---- O += P @ V (f16 mma; V B-frags via ldmatrix.trans) ----------
        #pragma unroll
        for (int ks = 0; ks < 4; ks++) {          // 64 kseq = 4 groups of 16
            int base = ks * 8;
            uint32_t a[4];
            a[0]=Ps[(r0+g  )*36 + base+t  ];
            a[1]=Ps[(r0+g+8)*36 + base+t  ];
            a[2]=Ps[(r0+g  )*36 + base+t+4];
            a[3]=Ps[(r0+g+8)*36 + base+t+4];
            #pragma unroll
            for (int p = 0; p < 4; p++) {         // d16 pair -> ni 2p, 2p+1
                uint32_t b0,b1,b2,b3;
                uint32_t addr = vbase
                    + (uint32_t)((ks*16 + (lane & 15)) * 272        // row k: 68 words
                    + (wn*64 + p*16 + ((lane >> 4) << 3)) * 2);     // col d in halves
                asm volatile(
                    "ldmatrix.sync.aligned.m8n8.x4.trans.shared.b16 {%0,%1,%2,%3}, [%4];"
                    : "=r"(b0),"=r"(b1),"=r"(b2),"=r"(b3) : "r"(addr));
                uint32_t bb0[2]={b0,b1}, bb1[2]={b2,b3};
                mma16(O[2*p],   a, bb0);
                mma16(O[2*p+1], a, bb1);
            }
        }
    }

    float inv0 = 1.f / l_r[0], inv1 = 1.f / l_r[1];
    int rg0 = q0 + r0 + g, rg1 = rg0 + 8;
    #pragma unroll
    for (int ni=0;ni<8;ni++){
        int c = h*HD + wn*64 + ni*8 + 2*t;        // even
        int cw = c >> 1;
        g_AttOh[((size_t)(b*SS)+rg0)*(DD/2) + cw] = f2h2(O[ni][0]*inv0, O[ni][1]*inv0);
        g_AttOh[((size_t)(b*SS)+rg1)*(DD/2) + cw] = f2h2(O[ni][2]*inv1, O[ni][3]*inv1);
    }
}

// ---------------- launch ----------------------------------------------------
extern "C" void kernel_launch(void* const* d_in, const int* in_sizes, int n_in,
                              void* d_out, int out_size){
    const float* x  = (const float*)d_in[0];
    const float* fc = (const float*)d_in[1];
    const float* fs = (const float*)d_in[2];
    const float* wq = (const float*)d_in[3];
    const float* wk = (const float*)d_in[4];
    const float* wv = (const float*)d_in[5];
    const float* wo = (const float*)d_in[6];
    float* out = (float*)d_out;

    uint32_t *pxh, *pwqkvh, *pwoh, *pAoh;
    cudaGetSymbolAddress((void**)&pxh,    g_xh);
    cudaGetSymbolAddress((void**)&pwqkvh, g_wqkvh);
    cudaGetSymbolAddress((void**)&pwoh,   g_woh);
    cudaGetSymbolAddress((void**)&pAoh,   g_AttOh);

    cudaFuncSetAttribute(gemm_h<0>, cudaFuncAttributeMaxDynamicSharedMemorySize, GH_SMEM);
    cudaFuncSetAttribute(gemm_h<1>, cudaFuncAttributeMaxDynamicSharedMemorySize, GH_SMEM);
    cudaFuncSetAttribute(flash_f16_kernel,
        cudaFuncAttributeMaxDynamicSharedMemorySize, FLASH_SMEM);

    cvt_kernel<<<18432, 256>>>(x, wq, wk, wv, wo);                              // 0
    gemm_h<0><<<dim3(24,32),256,GH_SMEM>>>(pxh, pwqkvh, nullptr, fc, fs, NQKV, 2048); // 1
    flash_f16_kernel<<<dim3(32,32),256,FLASH_SMEM>>>();                         // 2
    gemm_h<1><<<dim3(16,32),256,GH_SMEM>>>(pAoh, pwoh, out, nullptr, nullptr, 2048, 2048); // 3
}

// round 14
// speedup vs baseline: 1.5331x; 1.0247x over previous
#include <cuda_runtime.h>
#include <cuda_fp16.h>
#include <math.h>
#include <stdint.h>

#define BB 2
#define SS 2048
#define DD 2048
#define HH 16
#define KVH 4
#define HD 128
#define MM (BB*SS)        // 4096 rows
#define KVD (KVH*HD)      // 512
#define NQKV (DD + 2*KVD) // 3072 stacked rows

// ---------------- scratch (device globals; no allocation allowed) ----------
__device__ uint32_t g_xh   [(size_t)MM*DD/2];     // x as half2 words
__device__ uint32_t g_wqkvh[(size_t)NQKV*DD/2];   // wq|wk|wv stacked, half2
__device__ uint32_t g_woh  [(size_t)DD*DD/2];
__device__ uint32_t g_QtW[(size_t)MM*DD/2];       // roped+scaled Q [b,h,s,d] half2
__device__ uint32_t g_KtW[(size_t)MM*KVD/2];      // roped K        [b,kh,s,d]
__device__ uint32_t g_VtW[(size_t)MM*KVD/2];      // V              [b,kh,s,d]
__device__ uint32_t g_AttOh[(size_t)MM*DD/2];     // attention out  [b,s,h*d] half2

// ---------------- helpers ----------------------------------------------------
__device__ __forceinline__ uint32_t f2h2(float x, float y){
    __half2 h = __floats2half2_rn(x, y);       // .x = low = first elem
    return *(uint32_t*)&h;
}
__device__ __forceinline__ void mma16(float* c, const uint32_t* a, const uint32_t* b){
    asm volatile("mma.sync.aligned.m16n8k16.row.col.f32.f16.f16.f32 "
        "{%0,%1,%2,%3}, {%4,%5,%6,%7}, {%8,%9}, {%0,%1,%2,%3};"
        : "+f"(c[0]),"+f"(c[1]),"+f"(c[2]),"+f"(c[3])
        : "r"(a[0]),"r"(a[1]),"r"(a[2]),"r"(a[3]),"r"(b[0]),"r"(b[1]));
}
// fp16-accumulate variant: D,C are 2 regs of half2 (row g: {c0,c1}, row g+8: {c2,c3})
__device__ __forceinline__ void mma16h(uint32_t* c, const uint32_t* a, const uint32_t* b){
    asm volatile("mma.sync.aligned.m16n8k16.row.col.f16.f16.f16.f16 "
        "{%0,%1}, {%2,%3,%4,%5}, {%6,%7}, {%0,%1};"
        : "+r"(c[0]),"+r"(c[1])
        : "r"(a[0]),"r"(a[1]),"r"(a[2]),"r"(a[3]),"r"(b[0]),"r"(b[1]));
}
__device__ __forceinline__ void ldmx4(uint32_t* r, uint32_t addr){
    asm volatile("ldmatrix.sync.aligned.m8n8.x4.shared.b16 {%0,%1,%2,%3}, [%4];"
        : "=r"(r[0]),"=r"(r[1]),"=r"(r[2]),"=r"(r[3]) : "r"(addr));
}
#define CP_ASYNC16(dst, src) \
    asm volatile("cp.async.cg.shared.global [%0], [%1], 16;" :: "r"(dst), "l"(src))
#define CP_COMMIT() asm volatile("cp.async.commit_group;")
#define CP_WAIT1()  asm volatile("cp.async.wait_group 1;" ::: "memory")
#define CP_WAIT0()  asm volatile("cp.async.wait_group 0;" ::: "memory")

// ---------------- fp32 -> fp16 conversion prep -------------------------------
// float4-granular. wq/wk/wv stack into g_wqkvh (rows 0-2047 | 2048-2559 | 2560-3071)
__global__ void cvt_kernel(const float* __restrict__ x,  const float* __restrict__ wq,
                           const float* __restrict__ wk, const float* __restrict__ wv,
                           const float* __restrict__ wo){
    size_t i = (size_t)blockIdx.x*256 + threadIdx.x;   // float4 index
    const float* src; uint32_t* dst;
    if      (i < 2097152u){ src = x;  dst = g_xh;                              }
    else if (i < 3145728u){ src = wq; dst = g_wqkvh;            i -= 2097152u; }
    else if (i < 3407872u){ src = wk; dst = g_wqkvh + 2097152u; i -= 3145728u; }
    else if (i < 3670016u){ src = wv; dst = g_wqkvh + 2621440u; i -= 3407872u; }
    else                  { src = wo; dst = g_woh;              i -= 3670016u; }
    float4 v = ((const float4*)src)[i];
    dst[2*i]   = f2h2(v.x, v.y);
    dst[2*i+1] = f2h2(v.z, v.w);
}

// ---------------- half GEMM: C[M,N] = A[M,K] @ W[N,K]^T ---------------------
// R11-proven skeleton: block tile 128x128, k-step 64 halves, cp.async double
// buffer (loads issued in the wait shadow), ldmatrix fragments, 8 warps.
// MODE 0: fused QKV epilogue; MODE 1: plain f32 C (O-projection).
#define GH_ROWB 144u                 // 64 halves + 8 pad = 144 bytes/row
#define GH_TILE (128u*GH_ROWB)       // 18432 B per operand tile
#define GH_BUF  (2u*GH_TILE)         // A+B per buffer
#define GH_SMEM (2*GH_BUF)           // 73728 B

template<int MODE>
__global__ void __launch_bounds__(256,2) gemm_h(const uint32_t* __restrict__ A,
                                                const uint32_t* __restrict__ W,
                                                float* __restrict__ C,
                                                const float* __restrict__ cs,
                                                const float* __restrict__ sn,
                                                int N, int K)
{
    extern __shared__ char smem[];
    const uint32_t sb = (uint32_t)__cvta_generic_to_shared(smem);
    const int tid  = threadIdx.x;
    const int warp = tid >> 5, lane = tid & 31;
    const int g = lane >> 2, t = lane & 3;
    const int wm = warp & 1, wn = warp >> 1;
    const int m0 = blockIdx.y * 128, n0 = blockIdx.x * 128;
    const int KW = K >> 1;                         // half2 words per row

    const uint32_t* Ag = A + (size_t)m0 * KW;
    const uint32_t* Wg = W + (size_t)n0 * KW;

    float acc[4][4][4];
    #pragma unroll
    for (int a=0;a<4;a++)
        #pragma unroll
        for (int b2=0;b2<4;b2++)
            #pragma unroll
            for (int c=0;c<4;c++) acc[a][b2][c]=0.f;

    // per-thread cp.async map: 4 (row,chunk) pairs per operand
    int crow[4], cch[4];
    #pragma unroll
    for (int j=0;j<4;j++){ int idx = tid + j*256; crow[j]=idx>>3; cch[j]=idx&7; }

    auto load_tile = [&](int buf, int ktw){
        uint32_t sA = sb + buf*GH_BUF;
        uint32_t sB = sA + GH_TILE;
        #pragma unroll
        for (int j=0;j<4;j++){
            uint32_t off = crow[j]*GH_ROWB + cch[j]*16;
            const uint32_t* ga = Ag + (size_t)crow[j]*KW + ktw + cch[j]*4;
            const uint32_t* gb = Wg + (size_t)crow[j]*KW + ktw + cch[j]*4;
            CP_ASYNC16(sA + off, ga);
            CP_ASYNC16(sB + off, gb);
        }
    };

    const int NT = KW / 32;                        // k64-half tiles
    load_tile(0, 0); CP_COMMIT();

    const int selA = lane >> 3, lr = lane & 7;
    for (int s2 = 0; s2 < NT; s2++){
        const int buf = s2 & 1;
        if (s2 + 1 < NT){ load_tile(buf^1, (s2+1)*32); CP_COMMIT(); CP_WAIT1(); }
        else            { CP_WAIT0(); }
        __syncthreads();

        uint32_t sA = sb + buf*GH_BUF + (wm*64)*GH_ROWB;
        uint32_t sB = sb + buf*GH_BUF + GH_TILE + (wn*32)*GH_ROWB;
        #pragma unroll
        for (int kg = 0; kg < 4; kg++){
            uint32_t af[4][4], bf[4][2];
            #pragma unroll
            for (int mi=0; mi<4; mi++){
                uint32_t addr = sA + (mi*16 + (selA&1)*8 + lr)*GH_ROWB
                                   + (kg*16 + (selA>>1)*8)*2;
                ldmx4(af[mi], addr);
            }
            #pragma unroll
            for (int np=0; np<2; np++){
                uint32_t r[4];
                uint32_t addr = sB + (np*16 + (selA>>1)*8 + lr)*GH_ROWB
                                   + (kg*16 + (selA&1)*8)*2;
                ldmx4(r, addr);
                bf[np*2  ][0]=r[0]; bf[np*2  ][1]=r[1];
                bf[np*2+1][0]=r[2]; bf[np*2+1][1]=r[3];
            }
            #pragma unroll
            for (int mi=0; mi<4; mi++)
                #pragma unroll
                for (int ni=0; ni<4; ni++)
                    mma16(acc[mi][ni], af[mi], bf[ni]);
        }
        __syncthreads();
    }

    // ---------------- fused epilogues ---------------------------------------
    const float qs = 0.08838834764831845f;         // 1/sqrt(128)
    const int region = (MODE == 0) ? ((blockIdx.x < 16) ? 0 : (blockIdx.x < 20) ? 1 : 2) : 3;
    #pragma unroll
    for (int mi=0; mi<4; mi++){
        int r  = m0 + wm*64 + mi*16 + g;
        int r2 = r + 8;
        if (MODE == 1){
            #pragma unroll
            for (int ni=0; ni<4; ni++){
                int c = n0 + wn*32 + ni*8 + 2*t;
                *(float2*)(C + (size_t)r *N + c) = make_float2(acc[mi][ni][0], acc[mi][ni][1]);
                *(float2*)(C + (size_t)r2*N + c) = make_float2(acc[mi][ni][2], acc[mi][ni][3]);
            }
        } else {
            int b0 = r >> 11,  s0 = r  & (SS-1);
            int b1 = r2 >> 11, s1 = r2 & (SS-1);
            #pragma unroll
            for (int ni=0; ni<4; ni++){
                int c = n0 + wn*32 + ni*8 + 2*t;
                float a0=acc[mi][ni][0], a1=acc[mi][ni][1];
                float a2=acc[mi][ni][2], a3=acc[mi][ni][3];
                if (region == 0){                  // Q: rope + scale
                    int h = c >> 7, i = (c & 127) >> 1;
                    float cv0=cs[s0*64+i], sv0=sn[s0*64+i];
                    float cv1=cs[s1*64+i], sv1=sn[s1*64+i];
                    g_QtW[((size_t)(b0*HH+h)*SS + s0)*64 + i] =
                        f2h2((a0*cv0 - a1*sv0)*qs, (a0*sv0 + a1*cv0)*qs);
                    g_QtW[((size_t)(b1*HH+h)*SS + s1)*64 + i] =
                        f2h2((a2*cv1 - a3*sv1)*qs, (a2*sv1 + a3*cv1)*qs);
                } else if (region == 1){           // K: rope
                    int ck = c - 2048;
                    int h = ck >> 7, i = (ck & 127) >> 1;
                    float cv0=cs[s0*64+i], sv0=sn[s0*64+i];
                    float cv1=cs[s1*64+i], sv1=sn[s1*64+i];
                    g_KtW[((size_t)(b0*KVH+h)*SS + s0)*64 + i] =
                        f2h2(a0*cv0 - a1*sv0, a0*sv0 + a1*cv0);
                    g_KtW[((size_t)(b1*KVH+h)*SS + s1)*64 + i] =
                        f2h2(a2*cv1 - a3*sv1, a2*sv1 + a3*cv1);
                } else {                           // V: transpose only
                    int cv = c - 2560;
                    int h = cv >> 7, i = (cv & 127) >> 1;
                    g_VtW[((size_t)(b0*KVH+h)*SS + s0)*64 + i] = f2h2(a0, a1);
                    g_VtW[((size_t)(b1*KVH+h)*SS + s1)*64 + i] = f2h2(a2, a3);
                }
            }
        }
    }
}

// ---------------- tensor-core flash attention (f16 mma, causal) -------------
// R11 skeleton; QK^T now uses fp16 ACCUMULATION (mma...f16) — 2x rate if the
// tensor ceiling is accum-precision-bound. Softmax + PV stay fp32-accum.
#define FQ_OFF 0          // Qs [64][68] half2 words (Q pre-scaled)
#define FK_OFF 4352       // Ks [64][68]
#define FV_OFF 8704       // Vs [64][68]  row-major [k][d] (ldmatrix.trans source)
#define FP_OFF 13056      // Ps [64][36]  half2 prob words
#define FRM_OFF 15360     // RedM [2][64] float
#define FRS_OFF 15488     // RedS [2][64] float
#define FLASH_SMEM (15616*4)

__global__ void __launch_bounds__(256) flash_f16_kernel(){
    extern __shared__ uint32_t sm[];
    uint32_t* Qs = sm + FQ_OFF;
    uint32_t* Ks = sm + FK_OFF;
    uint32_t* Vs = sm + FV_OFF;
    uint32_t* Ps = sm + FP_OFF;
    float* RedM = (float*)(sm + FRM_OFF);
    float* RedS = (float*)(sm + FRS_OFF);
    const uint32_t vbase = (uint32_t)__cvta_generic_to_shared(Vs);

    const int qt = 31 - blockIdx.x;          // heaviest tiles first
    const int bh = blockIdx.y;
    const int b = bh >> 4, h = bh & 15;
    const int kvh = h >> 2;
    const int q0 = qt * 64;
    const int tid = threadIdx.x;
    const int warp = tid >> 5, lane = tid & 31;
    const int g = lane >> 2, t = lane & 3;
    const int wm = warp & 3, wn = warp >> 2;
    const int r0 = wm * 16;

    const uint32_t* Qg = g_QtW + (size_t)(b*HH + h)   * SS * 64;
    const uint32_t* Kg = g_KtW + (size_t)(b*KVH + kvh)* SS * 64;
    const uint32_t* Vg = g_VtW + (size_t)(b*KVH + kvh)* SS * 64;

    for (int i = tid; i < 64*16; i += 256) {       // Q: 64 rows x 16 uint4
        int r = i >> 4, w4 = (i & 15) * 4;
        *(uint4*)(Qs + r*68 + w4) = *(const uint4*)(Qg + (size_t)(q0+r)*64 + w4);
    }

    float O[8][4];
    #pragma unroll
    for (int ni=0;ni<8;ni++)
        #pragma unroll
        for (int j=0;j<4;j++) O[ni][j]=0.f;
    float m_r[2] = {-INFINITY,-INFINITY};
    float l_r[2] = {0.f,0.f};

    for (int kti = 0; kti <= qt; kti++) {
        int k0 = kti * 64;
        __syncthreads();                          // prev consumers done with Ks/Vs
        for (int i = tid; i < 64*16; i += 256) {
            int r = i >> 4, w4 = (i & 15) * 4;
            *(uint4*)(Ks + r*68 + w4) = *(const uint4*)(Kg + (size_t)(k0+r)*64 + w4);
            *(uint4*)(Vs + r*68 + w4) = *(const uint4*)(Vg + (size_t)(k0+r)*64 + w4);
        }
        __syncthreads();

        // ---- S = Q @ K^T (f16 mma, FP16 ACCUM, k = HD = 8 groups of 16) ---
        uint32_t scp[4][2];
        #pragma unroll
        for (int ni=0;ni<4;ni++){ scp[ni][0]=0u; scp[ni][1]=0u; }
        #pragma unroll
        for (int ks = 0; ks < 8; ks++) {
            int base = ks * 8;                     // word offset of k16 group
            uint32_t a[4];
            a[0]=Qs[(r0+g  )*68 + base+t  ];
            a[1]=Qs[(r0+g+8)*68 + base+t  ];
            a[2]=Qs[(r0+g  )*68 + base+t+4];
            a[3]=Qs[(r0+g+8)*68 + base+t+4];
            #pragma unroll
            for (int ni=0;ni<4;ni++){
                int n = wn*32 + ni*8 + g;
                uint32_t bfr[2];
                bfr[0]=Ks[n*68 + base+t  ];
                bfr[1]=Ks[n*68 + base+t+4];
                mma16h(scp[ni], a, bfr);
            }
        }
        // unpack to f32 fragments: reg0 = row g {c0,c1}, reg1 = row g+8 {c2,c3}
        float sc[4][4];
        #pragma unroll
        for (int ni=0;ni<4;ni++){
            float2 lo = __half22float2(*(__half2*)&scp[ni][0]);
            float2 hi = __half22float2(*(__half2*)&scp[ni][1]);
            sc[ni][0]=lo.x; sc[ni][1]=lo.y; sc[ni][2]=hi.x; sc[ni][3]=hi.y;
        }

        if (kti == qt) {                          // causal mask on diagonal
            int rg0 = q0 + r0 + g, rg1 = rg0 + 8;
            #pragma unroll
            for (int ni=0;ni<4;ni++){
                int ck = k0 + wn*32 + ni*8 + 2*t;
                if (ck   > rg0) sc[ni][0] = -INFINITY;
                if (ck+1 > rg0) sc[ni][1] = -INFINITY;
                if (ck   > rg1) sc[ni][2] = -INFINITY;
                if (ck+1 > rg1) sc[ni][3] = -INFINITY;
            }
        }

        // ---- online softmax on fragments --------------------------------
        float mx0 = -INFINITY, mx1 = -INFINITY;
        #pragma unroll
        for (int ni=0;ni<4;ni++){
            mx0 = fmaxf(mx0, fmaxf(sc[ni][0], sc[ni][1]));
            mx1 = fmaxf(mx1, fmaxf(sc[ni][2], sc[ni][3]));
        }
        mx0 = fmaxf(mx0, __shfl_xor_sync(0xffffffffu, mx0, 1));
        mx0 = fmaxf(mx0, __shfl_xor_sync(0xffffffffu, mx0, 2));
        mx1 = fmaxf(mx1, __shfl_xor_sync(0xffffffffu, mx1, 1));
        mx1 = fmaxf(mx1, __shfl_xor_sync(0xffffffffu, mx1, 2));
        if (t == 0) {
            RedM[wn*64 + r0+g  ] = mx0;
            RedM[wn*64 + r0+g+8] = mx1;
        }
        __syncthreads();
        float mt0 = fmaxf(RedM[r0+g  ], RedM[64 + r0+g  ]);
        float mt1 = fmaxf(RedM[r0+g+8], RedM[64 + r0+g+8]);
        float mn0 = fmaxf(m_r[0], mt0), mn1 = fmaxf(m_r[1], mt1);
        float f0 = __expf(m_r[0] - mn0), f1 = __expf(m_r[1] - mn1);
        m_r[0] = mn0; m_r[1] = mn1;

        float s0 = 0.f, s1 = 0.f;
        #pragma unroll
        for (int ni=0;ni<4;ni++){
            float p0 = __expf(sc[ni][0] - mn0);
            float p1 = __expf(sc[ni][1] - mn0);
            float p2 = __expf(sc[ni][2] - mn1);
            float p3 = __expf(sc[ni][3] - mn1);
            s0 += p0 + p1; s1 += p2 + p3;
            int w = wn*16 + ni*4 + t;             // word = col/2
            Ps[(r0+g  )*36 + w] = f2h2(p0, p1);
            Ps[(r0+g+8)*36 + w] = f2h2(p2, p3);
        }
        s0 += __shfl_xor_sync(0xffffffffu, s0, 1);
        s0 += __shfl_xor_sync(0xffffffffu, s0, 2);
        s1 += __shfl_xor_sync(0xffffffffu, s1, 1);
        s1 += __shfl_xor_sync(0xffffffffu, s1, 2);
        if (t == 0) {
            RedS[wn*64 + r0+g  ] = s0;
            RedS[wn*64 + r0+g+8] = s1;
        }
        #pragma unroll
        for (int ni=0;ni<8;ni++){
            O[ni][0] *= f0; O[ni][1] *= f0;
            O[ni][2] *= f1; O[ni][3] *= f1;
        }
        __syncthreads();                          // Ps + sums visible
        l_r[0] = l_r[0]*f0 + RedS[r0+g  ] + RedS[64 + r0+g  ];
        l_r[1] = l_r[1]*f1 + RedS[r0+g+8] + RedS[64 + r0+g+8];

        // ---- O += P @ V (f16 mma, fp32 accum; V B-frags via ldmatrix.trans)
        #pragma unroll
        for (int ks = 0; ks < 4; ks++) {          // 64 kseq = 4 groups of 16
            int base = ks * 8;
            uint32_t a[4];
            a[0]=Ps[(r0+g  )*36 + base+t  ];
            a[1]=Ps[(r0+g+8)*36 + base+t  ];
            a[2]=Ps[(r0+g  )*36 + base+t+4];
            a[3]=Ps[(r0+g+8)*36 + base+t+4];
            #pragma unroll
            for (int p = 0; p < 4; p++) {         // d16 pair -> ni 2p, 2p+1
                uint32_t b0,b1,b2,b3;
                uint32_t addr = vbase
                    + (uint32_t)((ks*16 + (lane & 15)) * 272        // row k: 68 words
                    + (wn*64 + p*16 + ((lane >> 4) << 3)) * 2);     // col d in halves
                asm volatile(
                    "ldmatrix.sync.aligned.m8n8.x4.trans.shared.b16 {%0,%1,%2,%3}, [%4];"
                    : "=r"(b0),"=r"(b1),"=r"(b2),"=r"(b3) : "r"(addr));
                uint32_t bb0[2]={b0,b1}, bb1[2]={b2,b3};
                mma16(O[2*p],   a, bb0);
                mma16(O[2*p+1], a, bb1);
            }
        }
    }

    float inv0 = 1.f / l_r[0], inv1 = 1.f / l_r[1];
    int rg0 = q0 + r0 + g, rg1 = rg0 + 8;
    #pragma unroll
    for (int ni=0;ni<8;ni++){
        int c = h*HD + wn*64 + ni*8 + 2*t;        // even
        int cw = c >> 1;
        g_AttOh[((size_t)(b*SS)+rg0)*(DD/2) + cw] = f2h2(O[ni][0]*inv0, O[ni][1]*inv0);
        g_AttOh[((size_t)(b*SS)+rg1)*(DD/2) + cw] = f2h2(O[ni][2]*inv1, O[ni][3]*inv1);
    }
}

// ---------------- launch ----------------------------------------------------
extern "C" void kernel_launch(void* const* d_in, const int* in_sizes, int n_in,
                              void* d_out, int out_size){
    const float* x  = (const float*)d_in[0];
    const float* fc = (const float*)d_in[1];
    const float* fs = (const float*)d_in[2];
    const float* wq = (const float*)d_in[3];
    const float* wk = (const float*)d_in[4];
    const float* wv = (const float*)d_in[5];
    const float* wo = (const float*)d_in[6];
    float* out = (float*)d_out;

    uint32_t *pxh, *pwqkvh, *pwoh, *pAoh;
    cudaGetSymbolAddress((void**)&pxh,    g_xh);
    cudaGetSymbolAddress((void**)&pwqkvh, g_wqkvh);
    cudaGetSymbolAddress((void**)&pwoh,   g_woh);
    cudaGetSymbolAddress((void**)&pAoh,   g_AttOh);

    cudaFuncSetAttribute(gemm_h<0>, cudaFuncAttributeMaxDynamicSharedMemorySize, GH_SMEM);
    cudaFuncSetAttribute(gemm_h<1>, cudaFuncAttributeMaxDynamicSharedMemorySize, GH_SMEM);
    cudaFuncSetAttribute(flash_f16_kernel,
        cudaFuncAttributeMaxDynamicSharedMemorySize, FLASH_SMEM);

    cvt_kernel<<<18432, 256>>>(x, wq, wk, wv, wo);                              // 0
    gemm_h<0><<<dim3(24,32),256,GH_SMEM>>>(pxh, pwqkvh, nullptr, fc, fs, NQKV, 2048); // 1
    flash_f16_kernel<<<dim3(32,32),256,FLASH_SMEM>>>();                         // 2
    gemm_h<1><<<dim3(16,32),256,GH_SMEM>>>(pAoh, pwoh, out, nullptr, nullptr, 2048, 2048); // 3
}

// round 15
// speedup vs baseline: 1.5987x; 1.0428x over previous
#include <cuda_runtime.h>
#include <cuda_fp16.h>
#include <math.h>
#include <stdint.h>

#define BB 2
#define SS 2048
#define DD 2048
#define HH 16
#define KVH 4
#define HD 128
#define MM (BB*SS)        // 4096 rows
#define KVD (KVH*HD)      // 512
#define NQKV (DD + 2*KVD) // 3072 stacked rows

// ---------------- scratch (device globals; no allocation allowed) ----------
__device__ uint32_t g_xh   [(size_t)MM*DD/2];     // x as half2 words
__device__ uint32_t g_wqkvh[(size_t)NQKV*DD/2];   // wq|wk|wv stacked, half2
__device__ uint32_t g_woh  [(size_t)DD*DD/2];
__device__ uint32_t g_QtW[(size_t)MM*DD/2];       // roped+scaled Q [b,h,s,d] half2
__device__ uint32_t g_KtW[(size_t)MM*KVD/2];      // roped K        [b,kh,s,d]
__device__ uint32_t g_VtW[(size_t)MM*KVD/2];      // V              [b,kh,s,d]
__device__ uint32_t g_AttOh[(size_t)MM*DD/2];     // attention out  [b,s,h*d] half2

// ---------------- helpers ----------------------------------------------------
__device__ __forceinline__ uint32_t f2h2(float x, float y){
    __half2 h = __floats2half2_rn(x, y);       // .x = low = first elem
    return *(uint32_t*)&h;
}
__device__ __forceinline__ void mma16(float* c, const uint32_t* a, const uint32_t* b){
    asm volatile("mma.sync.aligned.m16n8k16.row.col.f32.f16.f16.f32 "
        "{%0,%1,%2,%3}, {%4,%5,%6,%7}, {%8,%9}, {%0,%1,%2,%3};"
        : "+f"(c[0]),"+f"(c[1]),"+f"(c[2]),"+f"(c[3])
        : "r"(a[0]),"r"(a[1]),"r"(a[2]),"r"(a[3]),"r"(b[0]),"r"(b[1]));
}
// fp16-accumulate variant: D,C are 2 regs of half2 (row g: {c0,c1}, row g+8: {c2,c3})
__device__ __forceinline__ void mma16h(uint32_t* c, const uint32_t* a, const uint32_t* b){
    asm volatile("mma.sync.aligned.m16n8k16.row.col.f16.f16.f16.f16 "
        "{%0,%1}, {%2,%3,%4,%5}, {%6,%7}, {%0,%1};"
        : "+r"(c[0]),"+r"(c[1])
        : "r"(a[0]),"r"(a[1]),"r"(a[2]),"r"(a[3]),"r"(b[0]),"r"(b[1]));
}
__device__ __forceinline__ void ldmx4(uint32_t* r, uint32_t addr){
    asm volatile("ldmatrix.sync.aligned.m8n8.x4.shared.b16 {%0,%1,%2,%3}, [%4];"
        : "=r"(r[0]),"=r"(r[1]),"=r"(r[2]),"=r"(r[3]) : "r"(addr));
}
#define CP_ASYNC16(dst, src) \
    asm volatile("cp.async.cg.shared.global [%0], [%1], 16;" :: "r"(dst), "l"(src))
#define CP_COMMIT() asm volatile("cp.async.commit_group;")
#define CP_WAIT1()  asm volatile("cp.async.wait_group 1;" ::: "memory")
#define CP_WAIT0()  asm volatile("cp.async.wait_group 0;" ::: "memory")

// ---------------- fp32 -> fp16 conversion prep -------------------------------
// float4-granular. wq/wk/wv stack into g_wqkvh (rows 0-2047 | 2048-2559 | 2560-3071)
__global__ void cvt_kernel(const float* __restrict__ x,  const float* __restrict__ wq,
                           const float* __restrict__ wk, const float* __restrict__ wv,
                           const float* __restrict__ wo){
    size_t i = (size_t)blockIdx.x*256 + threadIdx.x;   // float4 index
    const float* src; uint32_t* dst;
    if      (i < 2097152u){ src = x;  dst = g_xh;                              }
    else if (i < 3145728u){ src = wq; dst = g_wqkvh;            i -= 2097152u; }
    else if (i < 3407872u){ src = wk; dst = g_wqkvh + 2097152u; i -= 3145728u; }
    else if (i < 3670016u){ src = wv; dst = g_wqkvh + 2621440u; i -= 3407872u; }
    else                  { src = wo; dst = g_woh;              i -= 3670016u; }
    float4 v = ((const float4*)src)[i];
    dst[2*i]   = f2h2(v.x, v.y);
    dst[2*i+1] = f2h2(v.z, v.w);
}

// ---------------- half GEMM: C[M,N] = A[M,K] @ W[N,K]^T ---------------------
// R11-proven skeleton: block tile 128x128, k-step 64 halves, cp.async double
// buffer (loads issued in the wait shadow), ldmatrix fragments, 8 warps.
// MODE 0: fused QKV epilogue; MODE 1: plain f32 C (O-projection).
#define GH_ROWB 144u                 // 64 halves + 8 pad = 144 bytes/row
#define GH_TILE (128u*GH_ROWB)       // 18432 B per operand tile
#define GH_BUF  (2u*GH_TILE)         // A+B per buffer
#define GH_SMEM (2*GH_BUF)           // 73728 B

template<int MODE>
__global__ void __launch_bounds__(256,2) gemm_h(const uint32_t* __restrict__ A,
                                                const uint32_t* __restrict__ W,
                                                float* __restrict__ C,
                                                const float* __restrict__ cs,
                                                const float* __restrict__ sn,
                                                int N, int K)
{
    extern __shared__ char smem[];
    const uint32_t sb = (uint32_t)__cvta_generic_to_shared(smem);
    const int tid  = threadIdx.x;
    const int warp = tid >> 5, lane = tid & 31;
    const int g = lane >> 2, t = lane & 3;
    const int wm = warp & 1, wn = warp >> 1;
    const int m0 = blockIdx.y * 128, n0 = blockIdx.x * 128;
    const int KW = K >> 1;                         // half2 words per row

    const uint32_t* Ag = A + (size_t)m0 * KW;
    const uint32_t* Wg = W + (size_t)n0 * KW;

    float acc[4][4][4];
    #pragma unroll
    for (int a=0;a<4;a++)
        #pragma unroll
        for (int b2=0;b2<4;b2++)
            #pragma unroll
            for (int c=0;c<4;c++) acc[a][b2][c]=0.f;

    // per-thread cp.async map: 4 (row,chunk) pairs per operand
    int crow[4], cch[4];
    #pragma unroll
    for (int j=0;j<4;j++){ int idx = tid + j*256; crow[j]=idx>>3; cch[j]=idx&7; }

    auto load_tile = [&](int buf, int ktw){
        uint32_t sA = sb + buf*GH_BUF;
        uint32_t sB = sA + GH_TILE;
        #pragma unroll
        for (int j=0;j<4;j++){
            uint32_t off = crow[j]*GH_ROWB + cch[j]*16;
            const uint32_t* ga = Ag + (size_t)crow[j]*KW + ktw + cch[j]*4;
            const uint32_t* gb = Wg + (size_t)crow[j]*KW + ktw + cch[j]*4;
            CP_ASYNC16(sA + off, ga);
            CP_ASYNC16(sB + off, gb);
        }
    };

    const int NT = KW / 32;                        // k64-half tiles
    load_tile(0, 0); CP_COMMIT();

    const int selA = lane >> 3, lr = lane & 7;
    for (int s2 = 0; s2 < NT; s2++){
        const int buf = s2 & 1;
        if (s2 + 1 < NT){ load_tile(buf^1, (s2+1)*32); CP_COMMIT(); CP_WAIT1(); }
        else            { CP_WAIT0(); }
        __syncthreads();

        uint32_t sA = sb + buf*GH_BUF + (wm*64)*GH_ROWB;
        uint32_t sB = sb + buf*GH_BUF + GH_TILE + (wn*32)*GH_ROWB;
        #pragma unroll
        for (int kg = 0; kg < 4; kg++){
            uint32_t af[4][4], bf[4][2];
            #pragma unroll
            for (int mi=0; mi<4; mi++){
                uint32_t addr = sA + (mi*16 + (selA&1)*8 + lr)*GH_ROWB
                                   + (kg*16 + (selA>>1)*8)*2;
                ldmx4(af[mi], addr);
            }
            #pragma unroll
            for (int np=0; np<2; np++){
                uint32_t r[4];
                uint32_t addr = sB + (np*16 + (selA>>1)*8 + lr)*GH_ROWB
                                   + (kg*16 + (selA&1)*8)*2;
                ldmx4(r, addr);
                bf[np*2  ][0]=r[0]; bf[np*2  ][1]=r[1];
                bf[np*2+1][0]=r[2]; bf[np*2+1][1]=r[3];
            }
            #pragma unroll
            for (int mi=0; mi<4; mi++)
                #pragma unroll
                for (int ni=0; ni<4; ni++)
                    mma16(acc[mi][ni], af[mi], bf[ni]);
        }
        __syncthreads();
    }

    // ---------------- fused epilogues ---------------------------------------
    const float qs = 0.08838834764831845f;         // 1/sqrt(128)
    const int region = (MODE == 0) ? ((blockIdx.x < 16) ? 0 : (blockIdx.x < 20) ? 1 : 2) : 3;
    #pragma unroll
    for (int mi=0; mi<4; mi++){
        int r  = m0 + wm*64 + mi*16 + g;
        int r2 = r + 8;
        if (MODE == 1){
            #pragma unroll
            for (int ni=0; ni<4; ni++){
                int c = n0 + wn*32 + ni*8 + 2*t;
                *(float2*)(C + (size_t)r *N + c) = make_float2(acc[mi][ni][0], acc[mi][ni][1]);
                *(float2*)(C + (size_t)r2*N + c) = make_float2(acc[mi][ni][2], acc[mi][ni][3]);
            }
        } else {
            int b0 = r >> 11,  s0 = r  & (SS-1);
            int b1 = r2 >> 11, s1 = r2 & (SS-1);
            #pragma unroll
            for (int ni=0; ni<4; ni++){
                int c = n0 + wn*32 + ni*8 + 2*t;
                float a0=acc[mi][ni][0], a1=acc[mi][ni][1];
                float a2=acc[mi][ni][2], a3=acc[mi][ni][3];
                if (region == 0){                  // Q: rope + scale
                    int h = c >> 7, i = (c & 127) >> 1;
                    float cv0=cs[s0*64+i], sv0=sn[s0*64+i];
                    float cv1=cs[s1*64+i], sv1=sn[s1*64+i];
                    g_QtW[((size_t)(b0*HH+h)*SS + s0)*64 + i] =
                        f2h2((a0*cv0 - a1*sv0)*qs, (a0*sv0 + a1*cv0)*qs);
                    g_QtW[((size_t)(b1*HH+h)*SS + s1)*64 + i] =
                        f2h2((a2*cv1 - a3*sv1)*qs, (a2*sv1 + a3*cv1)*qs);
                } else if (region == 1){           // K: rope
                    int ck = c - 2048;
                    int h = ck >> 7, i = (ck & 127) >> 1;
                    float cv0=cs[s0*64+i], sv0=sn[s0*64+i];
                    float cv1=cs[s1*64+i], sv1=sn[s1*64+i];
                    g_KtW[((size_t)(b0*KVH+h)*SS + s0)*64 + i] =
                        f2h2(a0*cv0 - a1*sv0, a0*sv0 + a1*cv0);
                    g_KtW[((size_t)(b1*KVH+h)*SS + s1)*64 + i] =
                        f2h2(a2*cv1 - a3*sv1, a2*sv1 + a3*cv1);
                } else {                           // V: transpose only
                    int cv = c - 2560;
                    int h = cv >> 7, i = (cv & 127) >> 1;
                    g_VtW[((size_t)(b0*KVH+h)*SS + s0)*64 + i] = f2h2(a0, a1);
                    g_VtW[((size_t)(b1*KVH+h)*SS + s1)*64 + i] = f2h2(a2, a3);
                }
            }
        }
    }
}

// ---------------- tensor-core flash attention (f16 mma, causal) -------------
// NEW: CTA = 128 q-rows, 8 warps x 16 rows each, warp owns COMPLETE S rows.
// Softmax fully warp-local (quad shfl only); P stays in registers (C-frag of
// QK, packed half2, IS the A-frag of PV). 2 barriers per k-tile, no P smem.
#define FQ_OFF 0            // Qs [128][68] half2 words (Q pre-scaled)
#define FK_OFF 8704         // Ks [64][68]
#define FV_OFF 13056        // Vs [64][68] row-major [k][d] (ldmatrix.trans src)
#define FLASH_SMEM (17408*4)

__global__ void __launch_bounds__(256,2) flash_f16_kernel(){
    extern __shared__ uint32_t sm[];
    uint32_t* Qs = sm + FQ_OFF;
    uint32_t* Ks = sm + FK_OFF;
    uint32_t* Vs = sm + FV_OFF;
    const uint32_t vbase = (uint32_t)__cvta_generic_to_shared(Vs);

    const int qt = 15 - blockIdx.x;          // heaviest q-tiles first
    const int bh = blockIdx.y;
    const int b = bh >> 4, h = bh & 15;
    const int kvh = h >> 2;
    const int q0 = qt * 128;
    const int tid = threadIdx.x;
    const int warp = tid >> 5, lane = tid & 31;
    const int g = lane >> 2, t = lane & 3;
    const int r0 = warp * 16;                // warp owns q-rows q0+r0 .. +15

    const uint32_t* Qg = g_QtW + (size_t)(b*HH + h)   * SS * 64;
    const uint32_t* Kg = g_KtW + (size_t)(b*KVH + kvh)* SS * 64;
    const uint32_t* Vg = g_VtW + (size_t)(b*KVH + kvh)* SS * 64;

    for (int i = tid; i < 128*16; i += 256) {      // Q: 128 rows x 16 uint4
        int r = i >> 4, w4 = (i & 15) * 4;
        *(uint4*)(Qs + r*68 + w4) = *(const uint4*)(Qg + (size_t)(q0+r)*64 + w4);
    }

    float O[16][4];
    #pragma unroll
    for (int ni=0;ni<16;ni++)
        #pragma unroll
        for (int j=0;j<4;j++) O[ni][j]=0.f;
    float m_r[2] = {-INFINITY,-INFINITY};
    float l_r[2] = {0.f,0.f};

    const int rg0 = q0 + r0 + g, rg1 = rg0 + 8;
    const int NT = 2*qt + 2;                       // causal k-tile count

    for (int kti = 0; kti < NT; kti++) {
        int k0 = kti * 64;
        __syncthreads();                           // prev consumers done with Ks/Vs
        for (int i = tid; i < 64*16; i += 256) {
            int r = i >> 4, w4 = (i & 15) * 4;
            *(uint4*)(Ks + r*68 + w4) = *(const uint4*)(Kg + (size_t)(k0+r)*64 + w4);
            *(uint4*)(Vs + r*68 + w4) = *(const uint4*)(Vg + (size_t)(k0+r)*64 + w4);
        }
        __syncthreads();                           // tile visible

        if (k0 > q0 + r0 + 15) continue;           // tile fully above warp rows
                                                   // (no barriers skipped)

        // ---- S = Q @ K^T (f16 mma, fp16 accum; 8 k16-groups, 8 n8-frags) --
        uint32_t scp[8][2];
        #pragma unroll
        for (int ni=0;ni<8;ni++){ scp[ni][0]=0u; scp[ni][1]=0u; }
        #pragma unroll
        for (int ks = 0; ks < 8; ks++) {
            int base = ks * 8;                     // word offset of k16 group
            uint32_t a[4];
            a[0]=Qs[(r0+g  )*68 + base+t  ];
            a[1]=Qs[(r0+g+8)*68 + base+t  ];
            a[2]=Qs[(r0+g  )*68 + base+t+4];
            a[3]=Qs[(r0+g+8)*68 + base+t+4];
            #pragma unroll
            for (int ni=0;ni<8;ni++){
                int n = ni*8 + g;
                uint32_t bfr[2];
                bfr[0]=Ks[n*68 + base+t  ];
                bfr[1]=Ks[n*68 + base+t+4];
                mma16h(scp[ni], a, bfr);
            }
        }
        // unpack: reg0 = row g {c0,c1}, reg1 = row g+8 {c2,c3}
        float sc[8][4];
        #pragma unroll
        for (int ni=0;ni<8;ni++){
            float2 lo = __half22float2(*(__half2*)&scp[ni][0]);
            float2 hi = __half22float2(*(__half2*)&scp[ni][1]);
            sc[ni][0]=lo.x; sc[ni][1]=lo.y; sc[ni][2]=hi.x; sc[ni][3]=hi.y;
        }

        if (k0 + 63 > rg0 - g) {                   // tile touches diagonal
            #pragma unroll
            for (int ni=0;ni<8;ni++){
                int ck = k0 + ni*8 + 2*t;
                if (ck   > rg0) sc[ni][0] = -INFINITY;
                if (ck+1 > rg0) sc[ni][1] = -INFINITY;
                if (ck   > rg1) sc[ni][2] = -INFINITY;
                if (ck+1 > rg1) sc[ni][3] = -INFINITY;
            }
        }

        // ---- warp-local online softmax (quad shfl only) -------------------
        float mx0 = -INFINITY, mx1 = -INFINITY;
        #pragma unroll
        for (int ni=0;ni<8;ni++){
            mx0 = fmaxf(mx0, fmaxf(sc[ni][0], sc[ni][1]));
            mx1 = fmaxf(mx1, fmaxf(sc[ni][2], sc[ni][3]));
        }
        mx0 = fmaxf(mx0, __shfl_xor_sync(0xffffffffu, mx0, 1));
        mx0 = fmaxf(mx0, __shfl_xor_sync(0xffffffffu, mx0, 2));
        mx1 = fmaxf(mx1, __shfl_xor_sync(0xffffffffu, mx1, 1));
        mx1 = fmaxf(mx1, __shfl_xor_sync(0xffffffffu, mx1, 2));
        float mn0 = fmaxf(m_r[0], mx0), mn1 = fmaxf(m_r[1], mx1);
        float f0 = __expf(m_r[0] - mn0), f1 = __expf(m_r[1] - mn1);
        m_r[0] = mn0; m_r[1] = mn1;

        uint32_t pk0[8], pk1[8];                   // P A-frags: row g / row g+8
        float s0 = 0.f, s1 = 0.f;
        #pragma unroll
        for (int ni=0;ni<8;ni++){
            float p0 = __expf(sc[ni][0] - mn0);
            float p1 = __expf(sc[ni][1] - mn0);
            float p2 = __expf(sc[ni][2] - mn1);
            float p3 = __expf(sc[ni][3] - mn1);
            s0 += p0 + p1; s1 += p2 + p3;
            pk0[ni] = f2h2(p0, p1);
            pk1[ni] = f2h2(p2, p3);
        }
        s0 += __shfl_xor_sync(0xffffffffu, s0, 1);
        s0 += __shfl_xor_sync(0xffffffffu, s0, 2);
        s1 += __shfl_xor_sync(0xffffffffu, s1, 1);
        s1 += __shfl_xor_sync(0xffffffffu, s1, 2);
        l_r[0] = l_r[0]*f0 + s0;
        l_r[1] = l_r[1]*f1 + s1;
        #pragma unroll
        for (int ni=0;ni<16;ni++){
            O[ni][0] *= f0; O[ni][1] *= f0;
            O[ni][2] *= f1; O[ni][3] *= f1;
        }

        // ---- O += P @ V (P from regs; V B-frags via ldmatrix.trans) -------
        #pragma unroll
        for (int ks = 0; ks < 4; ks++) {           // 64 kseq = 4 k16 groups
            uint32_t a[4] = { pk0[2*ks], pk1[2*ks], pk0[2*ks+1], pk1[2*ks+1] };
            #pragma unroll
            for (int p = 0; p < 8; p++) {          // d16 pair -> ni 2p, 2p+1
                uint32_t b0,b1,b2,b3;
                uint32_t addr = vbase
                    + (uint32_t)((ks*16 + (lane & 15)) * 272         // row k
                    + (p*16 + ((lane >> 4) << 3)) * 2);              // col d halves
                asm volatile(
                    "ldmatrix.sync.aligned.m8n8.x4.trans.shared.b16 {%0,%1,%2,%3}, [%4];"
                    : "=r"(b0),"=r"(b1),"=r"(b2),"=r"(b3) : "r"(addr));
                uint32_t bb0[2]={b0,b1}, bb1[2]={b2,b3};
                mma16(O[2*p],   a, bb0);
                mma16(O[2*p+1], a, bb1);
            }
        }
    }

    float inv0 = 1.f / l_r[0], inv1 = 1.f / l_r[1];
    #pragma unroll
    for (int ni=0;ni<16;ni++){
        int c = h*HD + ni*8 + 2*t;                 // even
        int cw = c >> 1;
        g_AttOh[((size_t)(b*SS)+rg0)*(DD/2) + cw] = f2h2(O[ni][0]*inv0, O[ni][1]*inv0);
        g_AttOh[((size_t)(b*SS)+rg1)*(DD/2) + cw] = f2h2(O[ni][2]*inv1, O[ni][3]*inv1);
    }
}

// ---------------- launch ----------------------------------------------------
extern "C" void kernel_launch(void* const* d_in, const int* in_sizes, int n_in,
                              void* d_out, int out_size){
    const float* x  = (const float*)d_in[0];
    const float* fc = (const float*)d_in[1];
    const float* fs = (const float*)d_in[2];
    const float* wq = (const float*)d_in[3];
    const float* wk = (const float*)d_in[4];
    const float* wv = (const float*)d_in[5];
    const float* wo = (const float*)d_in[6];
    float* out = (float*)d_out;

    uint32_t *pxh, *pwqkvh, *pwoh, *pAoh;
    cudaGetSymbolAddress((void**)&pxh,    g_xh);
    cudaGetSymbolAddress((void**)&pwqkvh, g_wqkvh);
    cudaGetSymbolAddress((void**)&pwoh,   g_woh);
    cudaGetSymbolAddress((void**)&pAoh,   g_AttOh);

    cudaFuncSetAttribute(gemm_h<0>, cudaFuncAttributeMaxDynamicSharedMemorySize, GH_SMEM);
    cudaFuncSetAttribute(gemm_h<1>, cudaFuncAttributeMaxDynamicSharedMemorySize, GH_SMEM);
    cudaFuncSetAttribute(flash_f16_kernel,
        cudaFuncAttributeMaxDynamicSharedMemorySize, FLASH_SMEM);

    cvt_kernel<<<18432, 256>>>(x, wq, wk, wv, wo);                              // 0
    gemm_h<0><<<dim3(24,32),256,GH_SMEM>>>(pxh, pwqkvh, nullptr, fc, fs, NQKV, 2048); // 1
    flash_f16_kernel<<<dim3(16,32),256,FLASH_SMEM>>>();                         // 2
    gemm_h<1><<<dim3(16,32),256,GH_SMEM>>>(pAoh, pwoh, out, nullptr, nullptr, 2048, 2048); // 3
}

// round 16
// speedup vs baseline: 1.6177x; 1.0119x over previous
#include <cuda_runtime.h>
#include <cuda_fp16.h>
#include <math.h>
#include <stdint.h>

#define BB 2
#define SS 2048
#define DD 2048
#define HH 16
#define KVH 4
#define HD 128
#define MM (BB*SS)        // 4096 rows
#define KVD (KVH*HD)      // 512
#define NQKV (DD + 2*KVD) // 3072 stacked rows

// ---------------- scratch (device globals; no allocation allowed) ----------
__device__ uint32_t g_xh   [(size_t)MM*DD/2];     // x as half2 words
__device__ uint32_t g_wqkvh[(size_t)NQKV*DD/2];   // wq|wk|wv stacked, half2
__device__ uint32_t g_woh  [(size_t)DD*DD/2];
__device__ uint32_t g_QtW[(size_t)MM*DD/2];       // roped+scaled Q [b,h,s,d] half2
__device__ uint32_t g_KtW[(size_t)MM*KVD/2];      // roped K        [b,kh,s,d]
__device__ uint32_t g_VtW[(size_t)MM*KVD/2];      // V              [b,kh,s,d]
__device__ uint32_t g_AttOh[(size_t)MM*DD/2];     // attention out  [b,s,h*d] half2

// ---------------- helpers ----------------------------------------------------
__device__ __forceinline__ uint32_t f2h2(float x, float y){
    __half2 h = __floats2half2_rn(x, y);       // .x = low = first elem
    return *(uint32_t*)&h;
}
__device__ __forceinline__ void mma16(float* c, const uint32_t* a, const uint32_t* b){
    asm volatile("mma.sync.aligned.m16n8k16.row.col.f32.f16.f16.f32 "
        "{%0,%1,%2,%3}, {%4,%5,%6,%7}, {%8,%9}, {%0,%1,%2,%3};"
        : "+f"(c[0]),"+f"(c[1]),"+f"(c[2]),"+f"(c[3])
        : "r"(a[0]),"r"(a[1]),"r"(a[2]),"r"(a[3]),"r"(b[0]),"r"(b[1]));
}
// fp16-accumulate variant: D,C are 2 regs of half2 (row g: {c0,c1}, row g+8: {c2,c3})
__device__ __forceinline__ void mma16h(uint32_t* c, const uint32_t* a, const uint32_t* b){
    asm volatile("mma.sync.aligned.m16n8k16.row.col.f16.f16.f16.f16 "
        "{%0,%1}, {%2,%3,%4,%5}, {%6,%7}, {%0,%1};"
        : "+r"(c[0]),"+r"(c[1])
        : "r"(a[0]),"r"(a[1]),"r"(a[2]),"r"(a[3]),"r"(b[0]),"r"(b[1]));
}
__device__ __forceinline__ void ldmx4(uint32_t* r, uint32_t addr){
    asm volatile("ldmatrix.sync.aligned.m8n8.x4.shared.b16 {%0,%1,%2,%3}, [%4];"
        : "=r"(r[0]),"=r"(r[1]),"=r"(r[2]),"=r"(r[3]) : "r"(addr));
}
#define CP_ASYNC16(dst, src) \
    asm volatile("cp.async.cg.shared.global [%0], [%1], 16;" :: "r"(dst), "l"(src))
#define CP_COMMIT() asm volatile("cp.async.commit_group;")
#define CP_WAIT1()  asm volatile("cp.async.wait_group 1;" ::: "memory")
#define CP_WAIT0()  asm volatile("cp.async.wait_group 0;" ::: "memory")

// ---------------- fp32 -> fp16 conversion prep -------------------------------
// float4-granular. wq/wk/wv stack into g_wqkvh (rows 0-2047 | 2048-2559 | 2560-3071)
__global__ void cvt_kernel(const float* __restrict__ x,  const float* __restrict__ wq,
                           const float* __restrict__ wk, const float* __restrict__ wv,
                           const float* __restrict__ wo){
    size_t i = (size_t)blockIdx.x*256 + threadIdx.x;   // float4 index
    const float* src; uint32_t* dst;
    if      (i < 2097152u){ src = x;  dst = g_xh;                              }
    else if (i < 3145728u){ src = wq; dst = g_wqkvh;            i -= 2097152u; }
    else if (i < 3407872u){ src = wk; dst = g_wqkvh + 2097152u; i -= 3145728u; }
    else if (i < 3670016u){ src = wv; dst = g_wqkvh + 2621440u; i -= 3407872u; }
    else                  { src = wo; dst = g_woh;              i -= 3670016u; }
    float4 v = ((const float4*)src)[i];
    dst[2*i]   = f2h2(v.x, v.y);
    dst[2*i+1] = f2h2(v.z, v.w);
}

// ---------------- half GEMM: C[M,N] = A[M,K] @ W[N,K]^T ---------------------
// R11-proven skeleton: block tile 128x128, k-step 64 halves, cp.async double
// buffer (loads issued in the wait shadow), ldmatrix fragments, 8 warps.
// MODE 0: fused QKV epilogue; MODE 1: plain f32 C (O-projection).
#define GH_ROWB 144u                 // 64 halves + 8 pad = 144 bytes/row
#define GH_TILE (128u*GH_ROWB)       // 18432 B per operand tile
#define GH_BUF  (2u*GH_TILE)         // A+B per buffer
#define GH_SMEM (2*GH_BUF)           // 73728 B

template<int MODE>
__global__ void __launch_bounds__(256,2) gemm_h(const uint32_t* __restrict__ A,
                                                const uint32_t* __restrict__ W,
                                                float* __restrict__ C,
                                                const float* __restrict__ cs,
                                                const float* __restrict__ sn,
                                                int N, int K)
{
    extern __shared__ char smem[];
    const uint32_t sb = (uint32_t)__cvta_generic_to_shared(smem);
    const int tid  = threadIdx.x;
    const int warp = tid >> 5, lane = tid & 31;
    const int g = lane >> 2, t = lane & 3;
    const int wm = warp & 1, wn = warp >> 1;
    const int m0 = blockIdx.y * 128, n0 = blockIdx.x * 128;
    const int KW = K >> 1;                         // half2 words per row

    const uint32_t* Ag = A + (size_t)m0 * KW;
    const uint32_t* Wg = W + (size_t)n0 * KW;

    float acc[4][4][4];
    #pragma unroll
    for (int a=0;a<4;a++)
        #pragma unroll
        for (int b2=0;b2<4;b2++)
            #pragma unroll
            for (int c=0;c<4;c++) acc[a][b2][c]=0.f;

    // per-thread cp.async map: 4 (row,chunk) pairs per operand
    int crow[4], cch[4];
    #pragma unroll
    for (int j=0;j<4;j++){ int idx = tid + j*256; crow[j]=idx>>3; cch[j]=idx&7; }

    auto load_tile = [&](int buf, int ktw){
        uint32_t sA = sb + buf*GH_BUF;
        uint32_t sB = sA + GH_TILE;
        #pragma unroll
        for (int j=0;j<4;j++){
            uint32_t off = crow[j]*GH_ROWB + cch[j]*16;
            const uint32_t* ga = Ag + (size_t)crow[j]*KW + ktw + cch[j]*4;
            const uint32_t* gb = Wg + (size_t)crow[j]*KW + ktw + cch[j]*4;
            CP_ASYNC16(sA + off, ga);
            CP_ASYNC16(sB + off, gb);
        }
    };

    const int NT = KW / 32;                        // k64-half tiles
    load_tile(0, 0); CP_COMMIT();

    const int selA = lane >> 3, lr = lane & 7;
    for (int s2 = 0; s2 < NT; s2++){
        const int buf = s2 & 1;
        if (s2 + 1 < NT){ load_tile(buf^1, (s2+1)*32); CP_COMMIT(); CP_WAIT1(); }
        else            { CP_WAIT0(); }
        __syncthreads();

        uint32_t sA = sb + buf*GH_BUF + (wm*64)*GH_ROWB;
        uint32_t sB = sb + buf*GH_BUF + GH_TILE + (wn*32)*GH_ROWB;
        #pragma unroll
        for (int kg = 0; kg < 4; kg++){
            uint32_t af[4][4], bf[4][2];
            #pragma unroll
            for (int mi=0; mi<4; mi++){
                uint32_t addr = sA + (mi*16 + (selA&1)*8 + lr)*GH_ROWB
                                   + (kg*16 + (selA>>1)*8)*2;
                ldmx4(af[mi], addr);
            }
            #pragma unroll
            for (int np=0; np<2; np++){
                uint32_t r[4];
                uint32_t addr = sB + (np*16 + (selA>>1)*8 + lr)*GH_ROWB
                                   + (kg*16 + (selA&1)*8)*2;
                ldmx4(r, addr);
                bf[np*2  ][0]=r[0]; bf[np*2  ][1]=r[1];
                bf[np*2+1][0]=r[2]; bf[np*2+1][1]=r[3];
            }
            #pragma unroll
            for (int mi=0; mi<4; mi++)
                #pragma unroll
                for (int ni=0; ni<4; ni++)
                    mma16(acc[mi][ni], af[mi], bf[ni]);
        }
        __syncthreads();
    }

    // ---------------- fused epilogues ---------------------------------------
    const float qs = 0.08838834764831845f;         // 1/sqrt(128)
    const int region = (MODE == 0) ? ((blockIdx.x < 16) ? 0 : (blockIdx.x < 20) ? 1 : 2) : 3;
    #pragma unroll
    for (int mi=0; mi<4; mi++){
        int r  = m0 + wm*64 + mi*16 + g;
        int r2 = r + 8;
        if (MODE == 1){
            #pragma unroll
            for (int ni=0; ni<4; ni++){
                int c = n0 + wn*32 + ni*8 + 2*t;
                *(float2*)(C + (size_t)r *N + c) = make_float2(acc[mi][ni][0], acc[mi][ni][1]);
                *(float2*)(C + (size_t)r2*N + c) = make_float2(acc[mi][ni][2], acc[mi][ni][3]);
            }
        } else {
            int b0 = r >> 11,  s0 = r  & (SS-1);
            int b1 = r2 >> 11, s1 = r2 & (SS-1);
            #pragma unroll
            for (int ni=0; ni<4; ni++){
                int c = n0 + wn*32 + ni*8 + 2*t;
                float a0=acc[mi][ni][0], a1=acc[mi][ni][1];
                float a2=acc[mi][ni][2], a3=acc[mi][ni][3];
                if (region == 0){                  // Q: rope + scale
                    int h = c >> 7, i = (c & 127) >> 1;
                    float cv0=cs[s0*64+i], sv0=sn[s0*64+i];
                    float cv1=cs[s1*64+i], sv1=sn[s1*64+i];
                    g_QtW[((size_t)(b0*HH+h)*SS + s0)*64 + i] =
                        f2h2((a0*cv0 - a1*sv0)*qs, (a0*sv0 + a1*cv0)*qs);
                    g_QtW[((size_t)(b1*HH+h)*SS + s1)*64 + i] =
                        f2h2((a2*cv1 - a3*sv1)*qs, (a2*sv1 + a3*cv1)*qs);
                } else if (region == 1){           // K: rope
                    int ck = c - 2048;
                    int h = ck >> 7, i = (ck & 127) >> 1;
                    float cv0=cs[s0*64+i], sv0=sn[s0*64+i];
                    float cv1=cs[s1*64+i], sv1=sn[s1*64+i];
                    g_KtW[((size_t)(b0*KVH+h)*SS + s0)*64 + i] =
                        f2h2(a0*cv0 - a1*sv0, a0*sv0 + a1*cv0);
                    g_KtW[((size_t)(b1*KVH+h)*SS + s1)*64 + i] =
                        f2h2(a2*cv1 - a3*sv1, a2*sv1 + a3*cv1);
                } else {                           // V: transpose only
                    int cv = c - 2560;
                    int h = cv >> 7, i = (cv & 127) >> 1;
                    g_VtW[((size_t)(b0*KVH+h)*SS + s0)*64 + i] = f2h2(a0, a1);
                    g_VtW[((size_t)(b1*KVH+h)*SS + s1)*64 + i] = f2h2(a2, a3);
                }
            }
        }
    }
}

// ---------------- tensor-core flash attention (f16 mma, causal) -------------
// CTA = 128 q-rows, 8 warps x 16 rows, warp-local softmax, P in registers.
// NEW: K/V double-buffered via cp.async (prefetch issued right after the single
// per-tile barrier — full-tile compute shadow); Q/K frags via ldmatrix.
#define FQ_OFF 0            // Qs [128][68] half2 words (Q pre-scaled)
#define FK_OFF 8704         // Ks[2] each 64*68
#define FV_OFF 17408        // Vs[2] each 64*68
#define FLASH_SMEM (26112*4)   // 104448 B

__global__ void __launch_bounds__(256,2) flash_f16_kernel(){
    extern __shared__ uint32_t sm[];
    uint32_t* Qs = sm + FQ_OFF;
    const uint32_t smB = (uint32_t)__cvta_generic_to_shared(sm);
    const uint32_t qB  = smB;                      // Q byte base

    const int qt = 15 - blockIdx.x;          // heaviest q-tiles first
    const int bh = blockIdx.y;
    const int b = bh >> 4, h = bh & 15;
    const int kvh = h >> 2;
    const int q0 = qt * 128;
    const int tid = threadIdx.x;
    const int warp = tid >> 5, lane = tid & 31;
    const int g = lane >> 2, t = lane & 3;
    const int r0 = warp * 16;                // warp owns q-rows q0+r0 .. +15
    const int selA = lane >> 3, lr = lane & 7;

    const uint32_t* Qg = g_QtW + (size_t)(b*HH + h)   * SS * 64;
    const uint32_t* Kg = g_KtW + (size_t)(b*KVH + kvh)* SS * 64;
    const uint32_t* Vg = g_VtW + (size_t)(b*KVH + kvh)* SS * 64;

    // async K+V tile load into buffer `buf` (2048 16B chunks, 8/thread)
    auto ldkv = [&](int k0, int buf){
        uint32_t kb = smB + (FK_OFF + buf*4352)*4;
        uint32_t vb = smB + (FV_OFF + buf*4352)*4;
        #pragma unroll
        for (int j = 0; j < 8; j++){
            int i = tid + j*256;
            int op = i >> 10, rem = i & 1023, r = rem >> 4, ch = rem & 15;
            const uint32_t* src = (op ? Vg : Kg) + (size_t)(k0+r)*64 + ch*4;
            uint32_t dst = (op ? vb : kb) + (uint32_t)(r*272 + ch*16);
            CP_ASYNC16(dst, src);
        }
    };

    for (int i = tid; i < 128*16; i += 256) {      // Q: 128 rows x 16 uint4
        int r = i >> 4, w4 = (i & 15) * 4;
        *(uint4*)(Qs + r*68 + w4) = *(const uint4*)(Qg + (size_t)(q0+r)*64 + w4);
    }
    ldkv(0, 0); CP_COMMIT();

    float O[16][4];
    #pragma unroll
    for (int ni=0;ni<16;ni++)
        #pragma unroll
        for (int j=0;j<4;j++) O[ni][j]=0.f;
    float m_r[2] = {-INFINITY,-INFINITY};
    float l_r[2] = {0.f,0.f};

    const int rg0 = q0 + r0 + g, rg1 = rg0 + 8;
    const int NT = 2*qt + 2;                       // causal k-tile count

    for (int kti = 0; kti < NT; kti++) {
        int k0 = kti * 64;
        const int buf = kti & 1;
        const uint32_t kB = smB + (FK_OFF + buf*4352)*4;
        const uint32_t vB = smB + (FV_OFF + buf*4352)*4;

        CP_WAIT0();
        __syncthreads();                           // tile kti visible; buf^1 dead
        if (kti + 1 < NT){ ldkv(k0 + 64, buf ^ 1); CP_COMMIT(); }

        if (k0 > q0 + r0 + 15) continue;           // tile fully above warp rows

        // ---- S = Q @ K^T (f16 mma, fp16 accum; frags via ldmatrix) --------
        uint32_t scp[8][2];
        #pragma unroll
        for (int ni=0;ni<8;ni++){ scp[ni][0]=0u; scp[ni][1]=0u; }
        #pragma unroll
        for (int ks = 0; ks < 8; ks++) {
            uint32_t a[4];
            ldmx4(a, qB + (uint32_t)((r0 + (selA&1)*8 + lr)*272
                                     + (ks*16 + (selA>>1)*8)*2));
            #pragma unroll
            for (int np=0; np<4; np++){
                uint32_t r[4];
                ldmx4(r, kB + (uint32_t)((np*16 + (selA>>1)*8 + lr)*272
                                         + (ks*16 + (selA&1)*8)*2));
                mma16h(scp[2*np  ], a, r);
                mma16h(scp[2*np+1], a, r+2);
            }
        }
        // unpack: reg0 = row g {c0,c1}, reg1 = row g+8 {c2,c3}
        float sc[8][4];
        #pragma unroll
        for (int ni=0;ni<8;ni++){
            float2 lo = __half22float2(*(__half2*)&scp[ni][0]);
            float2 hi = __half22float2(*(__half2*)&scp[ni][1]);
            sc[ni][0]=lo.x; sc[ni][1]=lo.y; sc[ni][2]=hi.x; sc[ni][3]=hi.y;
        }

        if (k0 + 63 > rg0 - g) {                   // tile touches diagonal
            #pragma unroll
            for (int ni=0;ni<8;ni++){
                int ck = k0 + ni*8 + 2*t;
                if (ck   > rg0) sc[ni][0] = -INFINITY;
                if (ck+1 > rg0) sc[ni][1] = -INFINITY;
                if (ck   > rg1) sc[ni][2] = -INFINITY;
                if (ck+1 > rg1) sc[ni][3] = -INFINITY;
            }
        }

        // ---- warp-local online softmax (quad shfl only) -------------------
        float mx0 = -INFINITY, mx1 = -INFINITY;
        #pragma unroll
        for (int ni=0;ni<8;ni++){
            mx0 = fmaxf(mx0, fmaxf(sc[ni][0], sc[ni][1]));
            mx1 = fmaxf(mx1, fmaxf(sc[ni][2], sc[ni][3]));
        }
        mx0 = fmaxf(mx0, __shfl_xor_sync(0xffffffffu, mx0, 1));
        mx0 = fmaxf(mx0, __shfl_xor_sync(0xffffffffu, mx0, 2));
        mx1 = fmaxf(mx1, __shfl_xor_sync(0xffffffffu, mx1, 1));
        mx1 = fmaxf(mx1, __shfl_xor_sync(0xffffffffu, mx1, 2));
        float mn0 = fmaxf(m_r[0], mx0), mn1 = fmaxf(m_r[1], mx1);
        float f0 = __expf(m_r[0] - mn0), f1 = __expf(m_r[1] - mn1);
        m_r[0] = mn0; m_r[1] = mn1;

        uint32_t pk0[8], pk1[8];                   // P A-frags: row g / row g+8
        float s0 = 0.f, s1 = 0.f;
        #pragma unroll
        for (int ni=0;ni<8;ni++){
            float p0 = __expf(sc[ni][0] - mn0);
            float p1 = __expf(sc[ni][1] - mn0);
            float p2 = __expf(sc[ni][2] - mn1);
            float p3 = __expf(sc[ni][3] - mn1);
            s0 += p0 + p1; s1 += p2 + p3;
            pk0[ni] = f2h2(p0, p1);
            pk1[ni] = f2h2(p2, p3);
        }
        s0 += __shfl_xor_sync(0xffffffffu, s0, 1);
        s0 += __shfl_xor_sync(0xffffffffu, s0, 2);
        s1 += __shfl_xor_sync(0xffffffffu, s1, 1);
        s1 += __shfl_xor_sync(0xffffffffu, s1, 2);
        l_r[0] = l_r[0]*f0 + s0;
        l_r[1] = l_r[1]*f1 + s1;
        #pragma unroll
        for (int ni=0;ni<16;ni++){
            O[ni][0] *= f0; O[ni][1] *= f0;
            O[ni][2] *= f1; O[ni][3] *= f1;
        }

        // ---- O += P @ V (P from regs; V B-frags via ldmatrix.trans) -------
        #pragma unroll
        for (int ks = 0; ks < 4; ks++) {           // 64 kseq = 4 k16 groups
            uint32_t a[4] = { pk0[2*ks], pk1[2*ks], pk0[2*ks+1], pk1[2*ks+1] };
            #pragma unroll
            for (int p = 0; p < 8; p++) {          // d16 pair -> ni 2p, 2p+1
                uint32_t b0,b1,b2,b3;
                uint32_t addr = vB
                    + (uint32_t)((ks*16 + (lane & 15)) * 272         // row k
                    + (p*16 + ((lane >> 4) << 3)) * 2);              // col d halves
                asm volatile(
                    "ldmatrix.sync.aligned.m8n8.x4.trans.shared.b16 {%0,%1,%2,%3}, [%4];"
                    : "=r"(b0),"=r"(b1),"=r"(b2),"=r"(b3) : "r"(addr));
                uint32_t bb0[2]={b0,b1}, bb1[2]={b2,b3};
                mma16(O[2*p],   a, bb0);
                mma16(O[2*p+1], a, bb1);
            }
        }
    }

    float inv0 = 1.f / l_r[0], inv1 = 1.f / l_r[1];
    #pragma unroll
    for (int ni=0;ni<16;ni++){
        int c = h*HD + ni*8 + 2*t;                 // even
        int cw = c >> 1;
        g_AttOh[((size_t)(b*SS)+rg0)*(DD/2) + cw] = f2h2(O[ni][0]*inv0, O[ni][1]*inv0);
        g_AttOh[((size_t)(b*SS)+rg1)*(DD/2) + cw] = f2h2(O[ni][2]*inv1, O[ni][3]*inv1);
    }
}

// ---------------- launch ----------------------------------------------------
extern "C" void kernel_launch(void* const* d_in, const int* in_sizes, int n_in,
                              void* d_out, int out_size){
    const float* x  = (const float*)d_in[0];
    const float* fc = (const float*)d_in[1];
    const float* fs = (const float*)d_in[2];
    const float* wq = (const float*)d_in[3];
    const float* wk = (const float*)d_in[4];
    const float* wv = (const float*)d_in[5];
    const float* wo = (const float*)d_in[6];
    float* out = (float*)d_out;

    uint32_t *pxh, *pwqkvh, *pwoh, *pAoh;
    cudaGetSymbolAddress((void**)&pxh,    g_xh);
    cudaGetSymbolAddress((void**)&pwqkvh, g_wqkvh);
    cudaGetSymbolAddress((void**)&pwoh,   g_woh);
    cudaGetSymbolAddress((void**)&pAoh,   g_AttOh);

    cudaFuncSetAttribute(gemm_h<0>, cudaFuncAttributeMaxDynamicSharedMemorySize, GH_SMEM);
    cudaFuncSetAttribute(gemm_h<1>, cudaFuncAttributeMaxDynamicSharedMemorySize, GH_SMEM);
    cudaFuncSetAttribute(flash_f16_kernel,
        cudaFuncAttributeMaxDynamicSharedMemorySize, FLASH_SMEM);

    cvt_kernel<<<18432, 256>>>(x, wq, wk, wv, wo);                              // 0
    gemm_h<0><<<dim3(24,32),256,GH_SMEM>>>(pxh, pwqkvh, nullptr, fc, fs, NQKV, 2048); // 1
    flash_f16_kernel<<<dim3(16,32),256,FLASH_SMEM>>>();                         // 2
    gemm_h<1><<<dim3(16,32),256,GH_SMEM>>>(pAoh, pwoh, out, nullptr, nullptr, 2048, 2048); // 3
}

// round 17
// speedup vs baseline: 1.8154x; 1.1222x over previous
#include <cuda_runtime.h>
#include <cuda_fp16.h>
#include <math.h>
#include <stdint.h>

#define BB 2
#define SS 2048
#define DD 2048
#define HH 16
#define KVH 4
#define HD 128
#define MM (BB*SS)        // 4096 rows
#define KVD (KVH*HD)      // 512
#define NQKV (DD + 2*KVD) // 3072 stacked rows

// ---------------- scratch (device globals; no allocation allowed) ----------
__device__ uint32_t g_xh   [(size_t)MM*DD/2];     // x as half2 words
__device__ uint32_t g_wqkvh[(size_t)NQKV*DD/2];   // wq|wk|wv stacked, half2
__device__ uint32_t g_woh  [(size_t)DD*DD/2];
__device__ uint32_t g_QtW[(size_t)MM*DD/2];       // roped, scaled by qs*log2e [b,h,s,d]
__device__ uint32_t g_KtW[(size_t)MM*KVD/2];      // roped K        [b,kh,s,d]
__device__ uint32_t g_VtW[(size_t)MM*KVD/2];      // V              [b,kh,s,d]
__device__ uint32_t g_AttOh[(size_t)MM*DD/2];     // attention out  [b,s,h*d] half2

// ---------------- helpers ----------------------------------------------------
__device__ __forceinline__ uint32_t f2h2(float x, float y){
    __half2 h = __floats2half2_rn(x, y);       // .x = low = first elem
    return *(uint32_t*)&h;
}
__device__ __forceinline__ void mma16(float* c, const uint32_t* a, const uint32_t* b){
    asm volatile("mma.sync.aligned.m16n8k16.row.col.f32.f16.f16.f32 "
        "{%0,%1,%2,%3}, {%4,%5,%6,%7}, {%8,%9}, {%0,%1,%2,%3};"
        : "+f"(c[0]),"+f"(c[1]),"+f"(c[2]),"+f"(c[3])
        : "r"(a[0]),"r"(a[1]),"r"(a[2]),"r"(a[3]),"r"(b[0]),"r"(b[1]));
}
// fp16-accumulate variant: D,C are 2 regs of half2 (row g: {c0,c1}, row g+8: {c2,c3})
__device__ __forceinline__ void mma16h(uint32_t* c, const uint32_t* a, const uint32_t* b){
    asm volatile("mma.sync.aligned.m16n8k16.row.col.f16.f16.f16.f16 "
        "{%0,%1}, {%2,%3,%4,%5}, {%6,%7}, {%0,%1};"
        : "+r"(c[0]),"+r"(c[1])
        : "r"(a[0]),"r"(a[1]),"r"(a[2]),"r"(a[3]),"r"(b[0]),"r"(b[1]));
}
__device__ __forceinline__ void ldmx4(uint32_t* r, uint32_t addr){
    asm volatile("ldmatrix.sync.aligned.m8n8.x4.shared.b16 {%0,%1,%2,%3}, [%4];"
        : "=r"(r[0]),"=r"(r[1]),"=r"(r[2]),"=r"(r[3]) : "r"(addr));
}
#define CP_ASYNC16(dst, src) \
    asm volatile("cp.async.cg.shared.global [%0], [%1], 16;" :: "r"(dst), "l"(src))
#define CP_COMMIT() asm volatile("cp.async.commit_group;")
#define CP_WAIT1()  asm volatile("cp.async.wait_group 1;" ::: "memory")
#define CP_WAIT0()  asm volatile("cp.async.wait_group 0;" ::: "memory")

// ---------------- fp32 -> fp16 conversion prep -------------------------------
// float4-granular. wq/wk/wv stack into g_wqkvh (rows 0-2047 | 2048-2559 | 2560-3071)
__global__ void cvt_kernel(const float* __restrict__ x,  const float* __restrict__ wq,
                           const float* __restrict__ wk, const float* __restrict__ wv,
                           const float* __restrict__ wo){
    size_t i = (size_t)blockIdx.x*256 + threadIdx.x;   // float4 index
    const float* src; uint32_t* dst;
    if      (i < 2097152u){ src = x;  dst = g_xh;                              }
    else if (i < 3145728u){ src = wq; dst = g_wqkvh;            i -= 2097152u; }
    else if (i < 3407872u){ src = wk; dst = g_wqkvh + 2097152u; i -= 3145728u; }
    else if (i < 3670016u){ src = wv; dst = g_wqkvh + 2621440u; i -= 3407872u; }
    else                  { src = wo; dst = g_woh;              i -= 3670016u; }
    float4 v = ((const float4*)src)[i];
    dst[2*i]   = f2h2(v.x, v.y);
    dst[2*i+1] = f2h2(v.z, v.w);
}

// ---------------- half GEMM: C[M,N] = A[M,K] @ W[N,K]^T ---------------------
// R11-proven skeleton: block tile 128x128, k-step 64 halves, cp.async double
// buffer (loads issued in the wait shadow), ldmatrix fragments, 8 warps.
// MODE 0: fused QKV epilogue; MODE 1: plain f32 C (O-projection).
#define GH_ROWB 144u                 // 64 halves + 8 pad = 144 bytes/row
#define GH_TILE (128u*GH_ROWB)       // 18432 B per operand tile
#define GH_BUF  (2u*GH_TILE)         // A+B per buffer
#define GH_SMEM (2*GH_BUF)           // 73728 B

template<int MODE>
__global__ void __launch_bounds__(256,2) gemm_h(const uint32_t* __restrict__ A,
                                                const uint32_t* __restrict__ W,
                                                float* __restrict__ C,
                                                const float* __restrict__ cs,
                                                const float* __restrict__ sn,
                                                int N, int K)
{
    extern __shared__ char smem[];
    const uint32_t sb = (uint32_t)__cvta_generic_to_shared(smem);
    const int tid  = threadIdx.x;
    const int warp = tid >> 5, lane = tid & 31;
    const int g = lane >> 2, t = lane & 3;
    const int wm = warp & 1, wn = warp >> 1;
    const int m0 = blockIdx.y * 128, n0 = blockIdx.x * 128;
    const int KW = K >> 1;                         // half2 words per row

    const uint32_t* Ag = A + (size_t)m0 * KW;
    const uint32_t* Wg = W + (size_t)n0 * KW;

    float acc[4][4][4];
    #pragma unroll
    for (int a=0;a<4;a++)
        #pragma unroll
        for (int b2=0;b2<4;b2++)
            #pragma unroll
            for (int c=0;c<4;c++) acc[a][b2][c]=0.f;

    // per-thread cp.async map: 4 (row,chunk) pairs per operand
    int crow[4], cch[4];
    #pragma unroll
    for (int j=0;j<4;j++){ int idx = tid + j*256; crow[j]=idx>>3; cch[j]=idx&7; }

    auto load_tile = [&](int buf, int ktw){
        uint32_t sA = sb + buf*GH_BUF;
        uint32_t sB = sA + GH_TILE;
        #pragma unroll
        for (int j=0;j<4;j++){
            uint32_t off = crow[j]*GH_ROWB + cch[j]*16;
            const uint32_t* ga = Ag + (size_t)crow[j]*KW + ktw + cch[j]*4;
            const uint32_t* gb = Wg + (size_t)crow[j]*KW + ktw + cch[j]*4;
            CP_ASYNC16(sA + off, ga);
            CP_ASYNC16(sB + off, gb);
        }
    };

    const int NT = KW / 32;                        // k64-half tiles
    load_tile(0, 0); CP_COMMIT();

    const int selA = lane >> 3, lr = lane & 7;
    for (int s2 = 0; s2 < NT; s2++){
        const int buf = s2 & 1;
        if (s2 + 1 < NT){ load_tile(buf^1, (s2+1)*32); CP_COMMIT(); CP_WAIT1(); }
        else            { CP_WAIT0(); }
        __syncthreads();

        uint32_t sA = sb + buf*GH_BUF + (wm*64)*GH_ROWB;
        uint32_t sB = sb + buf*GH_BUF + GH_TILE + (wn*32)*GH_ROWB;
        #pragma unroll
        for (int kg = 0; kg < 4; kg++){
            uint32_t af[4][4], bf[4][2];
            #pragma unroll
            for (int mi=0; mi<4; mi++){
                uint32_t addr = sA + (mi*16 + (selA&1)*8 + lr)*GH_ROWB
                                   + (kg*16 + (selA>>1)*8)*2;
                ldmx4(af[mi], addr);
            }
            #pragma unroll
            for (int np=0; np<2; np++){
                uint32_t r[4];
                uint32_t addr = sB + (np*16 + (selA>>1)*8 + lr)*GH_ROWB
                                   + (kg*16 + (selA&1)*8)*2;
                ldmx4(r, addr);
                bf[np*2  ][0]=r[0]; bf[np*2  ][1]=r[1];
                bf[np*2+1][0]=r[2]; bf[np*2+1][1]=r[3];
            }
            #pragma unroll
            for (int mi=0; mi<4; mi++)
                #pragma unroll
                for (int ni=0; ni<4; ni++)
                    mma16(acc[mi][ni], af[mi], bf[ni]);
        }
        __syncthreads();
    }

    // ---------------- fused epilogues ---------------------------------------
    // Q pre-scale: 1/sqrt(128) * log2(e)  (flash uses exp2 -> exact same math)
    const float qs = 0.08838834764831845f * 1.4426950408889634f;
    const int region = (MODE == 0) ? ((blockIdx.x < 16) ? 0 : (blockIdx.x < 20) ? 1 : 2) : 3;
    #pragma unroll
    for (int mi=0; mi<4; mi++){
        int r  = m0 + wm*64 + mi*16 + g;
        int r2 = r + 8;
        if (MODE == 1){
            #pragma unroll
            for (int ni=0; ni<4; ni++){
                int c = n0 + wn*32 + ni*8 + 2*t;
                *(float2*)(C + (size_t)r *N + c) = make_float2(acc[mi][ni][0], acc[mi][ni][1]);
                *(float2*)(C + (size_t)r2*N + c) = make_float2(acc[mi][ni][2], acc[mi][ni][3]);
            }
        } else {
            int b0 = r >> 11,  s0 = r  & (SS-1);
            int b1 = r2 >> 11, s1 = r2 & (SS-1);
            #pragma unroll
            for (int ni=0; ni<4; ni++){
                int c = n0 + wn*32 + ni*8 + 2*t;
                float a0=acc[mi][ni][0], a1=acc[mi][ni][1];
                float a2=acc[mi][ni][2], a3=acc[mi][ni][3];
                if (region == 0){                  // Q: rope + scale(incl log2e)
                    int h = c >> 7, i = (c & 127) >> 1;
                    float cv0=cs[s0*64+i], sv0=sn[s0*64+i];
                    float cv1=cs[s1*64+i], sv1=sn[s1*64+i];
                    g_QtW[((size_t)(b0*HH+h)*SS + s0)*64 + i] =
                        f2h2((a0*cv0 - a1*sv0)*qs, (a0*sv0 + a1*cv0)*qs);
                    g_QtW[((size_t)(b1*HH+h)*SS + s1)*64 + i] =
                        f2h2((a2*cv1 - a3*sv1)*qs, (a2*sv1 + a3*cv1)*qs);
                } else if (region == 1){           // K: rope
                    int ck = c - 2048;
                    int h = ck >> 7, i = (ck & 127) >> 1;
                    float cv0=cs[s0*64+i], sv0=sn[s0*64+i];
                    float cv1=cs[s1*64+i], sv1=sn[s1*64+i];
                    g_KtW[((size_t)(b0*KVH+h)*SS + s0)*64 + i] =
                        f2h2(a0*cv0 - a1*sv0, a0*sv0 + a1*cv0);
                    g_KtW[((size_t)(b1*KVH+h)*SS + s1)*64 + i] =
                        f2h2(a2*cv1 - a3*sv1, a2*sv1 + a3*cv1);
                } else {                           // V: transpose only
                    int cv = c - 2560;
                    int h = cv >> 7, i = (cv & 127) >> 1;
                    g_VtW[((size_t)(b0*KVH+h)*SS + s0)*64 + i] = f2h2(a0, a1);
                    g_VtW[((size_t)(b1*KVH+h)*SS + s1)*64 + i] = f2h2(a2, a3);
                }
            }
        }
    }
}

// ---------------- tensor-core flash attention (f16 mma, causal) -------------
// CTA = 128 q-rows, 8 warps x 16 rows, warp-local softmax, P in registers,
// cp.async double-buffered K/V, frags via ldmatrix.
// NEW: linear 512-CTA grid with ALL heavy q-tiles in wave 1:
//   bid 0..31 -> qt=15 (all bh), bid 32..63 -> qt=14, ... (backfill = light CTAs)
#define FQ_OFF 0            // Qs [128][68] half2 words (Q pre-scaled)
#define FK_OFF 8704         // Ks[2] each 64*68
#define FV_OFF 17408        // Vs[2] each 64*68
#define FLASH_SMEM (26112*4)   // 104448 B

__global__ void __launch_bounds__(256,2) flash_f16_kernel(){
    extern __shared__ uint32_t sm[];
    uint32_t* Qs = sm + FQ_OFF;
    const uint32_t smB = (uint32_t)__cvta_generic_to_shared(sm);
    const uint32_t qB  = smB;                      // Q byte base

    const int bid = blockIdx.x;
    const int qt = 15 - (bid >> 5);                // heavy tiles fill wave 1
    const int bh = bid & 31;
    const int b = bh >> 4, h = bh & 15;
    const int kvh = h >> 2;
    const int q0 = qt * 128;
    const int tid = threadIdx.x;
    const int warp = tid >> 5, lane = tid & 31;
    const int g = lane >> 2, t = lane & 3;
    const int r0 = warp * 16;                // warp owns q-rows q0+r0 .. +15
    const int selA = lane >> 3, lr = lane & 7;

    const uint32_t* Qg = g_QtW + (size_t)(b*HH + h)   * SS * 64;
    const uint32_t* Kg = g_KtW + (size_t)(b*KVH + kvh)* SS * 64;
    const uint32_t* Vg = g_VtW + (size_t)(b*KVH + kvh)* SS * 64;

    // async K+V tile load into buffer `buf` (2048 16B chunks, 8/thread)
    auto ldkv = [&](int k0, int buf){
        uint32_t kb = smB + (FK_OFF + buf*4352)*4;
        uint32_t vb = smB + (FV_OFF + buf*4352)*4;
        #pragma unroll
        for (int j = 0; j < 8; j++){
            int i = tid + j*256;
            int op = i >> 10, rem = i & 1023, r = rem >> 4, ch = rem & 15;
            const uint32_t* src = (op ? Vg : Kg) + (size_t)(k0+r)*64 + ch*4;
            uint32_t dst = (op ? vb : kb) + (uint32_t)(r*272 + ch*16);
            CP_ASYNC16(dst, src);
        }
    };

    for (int i = tid; i < 128*16; i += 256) {      // Q: 128 rows x 16 uint4
        int r = i >> 4, w4 = (i & 15) * 4;
        *(uint4*)(Qs + r*68 + w4) = *(const uint4*)(Qg + (size_t)(q0+r)*64 + w4);
    }
    ldkv(0, 0); CP_COMMIT();

    float O[16][4];
    #pragma unroll
    for (int ni=0;ni<16;ni++)
        #pragma unroll
        for (int j=0;j<4;j++) O[ni][j]=0.f;
    float m_r[2] = {-INFINITY,-INFINITY};
    float l_r[2] = {0.f,0.f};

    const int rg0 = q0 + r0 + g, rg1 = rg0 + 8;
    const int NT = 2*qt + 2;                       // causal k-tile count

    for (int kti = 0; kti < NT; kti++) {
        int k0 = kti * 64;
        const int buf = kti & 1;
        const uint32_t kB = smB + (FK_OFF + buf*4352)*4;
        const uint32_t vB = smB + (FV_OFF + buf*4352)*4;

        CP_WAIT0();
        __syncthreads();                           // tile kti visible; buf^1 dead
        if (kti + 1 < NT){ ldkv(k0 + 64, buf ^ 1); CP_COMMIT(); }

        if (k0 > q0 + r0 + 15) continue;           // tile fully above warp rows

        // ---- S = Q @ K^T (f16 mma, fp16 accum; frags via ldmatrix) --------
        uint32_t scp[8][2];
        #pragma unroll
        for (int ni=0;ni<8;ni++){ scp[ni][0]=0u; scp[ni][1]=0u; }
        #pragma unroll
        for (int ks = 0; ks < 8; ks++) {
            uint32_t a[4];
            ldmx4(a, qB + (uint32_t)((r0 + (selA&1)*8 + lr)*272
                                     + (ks*16 + (selA>>1)*8)*2));
            #pragma unroll
            for (int np=0; np<4; np++){
                uint32_t r[4];
                ldmx4(r, kB + (uint32_t)((np*16 + (selA>>1)*8 + lr)*272
                                         + (ks*16 + (selA&1)*8)*2));
                mma16h(scp[2*np  ], a, r);
                mma16h(scp[2*np+1], a, r+2);
            }
        }
        // unpack: reg0 = row g {c0,c1}, reg1 = row g+8 {c2,c3}
        float sc[8][4];
        #pragma unroll
        for (int ni=0;ni<8;ni++){
            float2 lo = __half22float2(*(__half2*)&scp[ni][0]);
            float2 hi = __half22float2(*(__half2*)&scp[ni][1]);
            sc[ni][0]=lo.x; sc[ni][1]=lo.y; sc[ni][2]=hi.x; sc[ni][3]=hi.y;
        }

        if (k0 + 63 > rg0 - g) {                   // tile touches diagonal
            #pragma unroll
            for (int ni=0;ni<8;ni++){
                int ck = k0 + ni*8 + 2*t;
                if (ck   > rg0) sc[ni][0] = -INFINITY;
                if (ck+1 > rg0) sc[ni][1] = -INFINITY;
                if (ck   > rg1) sc[ni][2] = -INFINITY;
                if (ck+1 > rg1) sc[ni][3] = -INFINITY;
            }
        }

        // ---- warp-local online softmax (quad shfl only; base-2 domain) ----
        float mx0 = -INFINITY, mx1 = -INFINITY;
        #pragma unroll
        for (int ni=0;ni<8;ni++){
            mx0 = fmaxf(mx0, fmaxf(sc[ni][0], sc[ni][1]));
            mx1 = fmaxf(mx1, fmaxf(sc[ni][2], sc[ni][3]));
        }
        mx0 = fmaxf(mx0, __shfl_xor_sync(0xffffffffu, mx0, 1));
        mx0 = fmaxf(mx0, __shfl_xor_sync(0xffffffffu, mx0, 2));
        mx1 = fmaxf(mx1, __shfl_xor_sync(0xffffffffu, mx1, 1));
        mx1 = fmaxf(mx1, __shfl_xor_sync(0xffffffffu, mx1, 2));
        float mn0 = fmaxf(m_r[0], mx0), mn1 = fmaxf(m_r[1], mx1);
        float f0 = exp2f(m_r[0] - mn0), f1 = exp2f(m_r[1] - mn1);
        m_r[0] = mn0; m_r[1] = mn1;

        uint32_t pk0[8], pk1[8];                   // P A-frags: row g / row g+8
        float s0 = 0.f, s1 = 0.f;
        #pragma unroll
        for (int ni=0;ni<8;ni++){
            float p0 = exp2f(sc[ni][0] - mn0);
            float p1 = exp2f(sc[ni][1] - mn0);
            float p2 = exp2f(sc[ni][2] - mn1);
            float p3 = exp2f(sc[ni][3] - mn1);
            s0 += p0 + p1; s1 += p2 + p3;
            pk0[ni] = f2h2(p0, p1);
            pk1[ni] = f2h2(p2, p3);
        }
        s0 += __shfl_xor_sync(0xffffffffu, s0, 1);
        s0 += __shfl_xor_sync(0xffffffffu, s0, 2);
        s1 += __shfl_xor_sync(0xffffffffu, s1, 1);
        s1 += __shfl_xor_sync(0xffffffffu, s1, 2);
        l_r[0] = l_r[0]*f0 + s0;
        l_r[1] = l_r[1]*f1 + s1;
        #pragma unroll
        for (int ni=0;ni<16;ni++){
            O[ni][0] *= f0; O[ni][1] *= f0;
            O[ni][2] *= f1; O[ni][3] *= f1;
        }

        // ---- O += P @ V (P from regs; V B-frags via ldmatrix.trans) -------
        #pragma unroll
        for (int ks = 0; ks < 4; ks++) {           // 64 kseq = 4 k16 groups
            uint32_t a[4] = { pk0[2*ks], pk1[2*ks], pk0[2*ks+1], pk1[2*ks+1] };
            #pragma unroll
            for (int p = 0; p < 8; p++) {          // d16 pair -> ni 2p, 2p+1
                uint32_t b0,b1,b2,b3;
                uint32_t addr = vB
                    + (uint32_t)((ks*16 + (lane & 15)) * 272         // row k
                    + (p*16 + ((lane >> 4) << 3)) * 2);              // col d halves
                asm volatile(
                    "ldmatrix.sync.aligned.m8n8.x4.trans.shared.b16 {%0,%1,%2,%3}, [%4];"
                    : "=r"(b0),"=r"(b1),"=r"(b2),"=r"(b3) : "r"(addr));
                uint32_t bb0[2]={b0,b1}, bb1[2]={b2,b3};
                mma16(O[2*p],   a, bb0);
                mma16(O[2*p+1], a, bb1);
            }
        }
    }

    float inv0 = 1.f / l_r[0], inv1 = 1.f / l_r[1];
    #pragma unroll
    for (int ni=0;ni<16;ni++){
        int c = h*HD + ni*8 + 2*t;                 // even
        int cw = c >> 1;
        g_AttOh[((size_t)(b*SS)+rg0)*(DD/2) + cw] = f2h2(O[ni][0]*inv0, O[ni][1]*inv0);
        g_AttOh[((size_t)(b*SS)+rg1)*(DD/2) + cw] = f2h2(O[ni][2]*inv1, O[ni][3]*inv1);
    }
}

// ---------------- launch ----------------------------------------------------
extern "C" void kernel_launch(void* const* d_in, const int* in_sizes, int n_in,
                              void* d_out, int out_size){
    const float* x  = (const float*)d_in[0];
    const float* fc = (const float*)d_in[1];
    const float* fs = (const float*)d_in[2];
    const float* wq = (const float*)d_in[3];
    const float* wk = (const float*)d_in[4];
    const float* wv = (const float*)d_in[5];
    const float* wo = (const float*)d_in[6];
    float* out = (float*)d_out;

    uint32_t *pxh, *pwqkvh, *pwoh, *pAoh;
    cudaGetSymbolAddress((void**)&pxh,    g_xh);
    cudaGetSymbolAddress((void**)&pwqkvh, g_wqkvh);
    cudaGetSymbolAddress((void**)&pwoh,   g_woh);
    cudaGetSymbolAddress((void**)&pAoh,   g_AttOh);

    cudaFuncSetAttribute(gemm_h<0>, cudaFuncAttributeMaxDynamicSharedMemorySize, GH_SMEM);
    cudaFuncSetAttribute(gemm_h<1>, cudaFuncAttributeMaxDynamicSharedMemorySize, GH_SMEM);
    cudaFuncSetAttribute(flash_f16_kernel,
        cudaFuncAttributeMaxDynamicSharedMemorySize, FLASH_SMEM);

    cvt_kernel<<<18432, 256>>>(x, wq, wk, wv, wo);                              // 0
    gemm_h<0><<<dim3(24,32),256,GH_SMEM>>>(pxh, pwqkvh, nullptr, fc, fs, NQKV, 2048); // 1
    flash_f16_kernel<<<512,256,FLASH_SMEM>>>();                                 // 2
    gemm_h<1><<<dim3(16,32),256,GH_SMEM>>>(pAoh, pwoh, out, nullptr, nullptr, 2048, 2048); // 3
}